// round 11
// baseline (speedup 1.0000x reference)
#include <cuda_runtime.h>
#include <cuda_fp16.h>
#include <math.h>

#define NN 100000
#define NE 1600000
#define ET 1700000          // NE + NN self loops
#define NB 98               // ceil(NN/1024)

// GEMM tiling
#define BM 128
#define BN 64
#define BK 16

// ---------------- static scratch (no allocations allowed) ----------------
__device__ __align__(256) __half g_hlh[NN * 128];   // hl fp16 (edge gather)
__device__ __align__(256) float  g_hr[NN * 128];
__device__ __align__(256) float  g_h [NN * 128];
__device__ __align__(256) __half g_wth[6 * 16384];  // W^T [oc][128], fp16 hi
__device__ __align__(256) __half g_wtl[6 * 16384];  // W^T lo residual
__device__ int g_deg[NN];
__device__ int g_tmp[NN];
__device__ int g_rowptr[NN + 1];
__device__ int g_fill[NN];
__device__ int g_esrc[ET];
__device__ int g_src[ET];
__device__ int g_dst[ET];
__device__ int g_bsums[128];
__device__ int g_is64;

// ---------------- ingestion + CSR + W convert ----------------
__global__ void zero_detect_k(const int* __restrict__ ei32,
                              const float* __restrict__ W0l, const float* __restrict__ W0r,
                              const float* __restrict__ W1l, const float* __restrict__ W1r,
                              const float* __restrict__ W2l, const float* __restrict__ W2r) {
    int i = blockIdx.x * blockDim.x + threadIdx.x;
    if (i < NN) g_deg[i] = 0;
    if (i == 0) {
        int acc = 0;
        for (int j = 0; j < 1024; j++) acc |= ei32[2 * j + 1];
        g_is64 = (acc == 0) ? 1 : 0;   // int64 little-endian => high words all 0
    }
    // W transpose + fp16 hi/lo split: Wt[oc][128] so k runs contiguous
    if (i < 4 * 16384) {
        int mat = i >> 14, idx = i & 16383;
        const float* Ws[4] = {W0l, W0r, W1l, W1r};
        float w = Ws[mat][idx];
        int k = idx >> 7, o = idx & 127;        // src W[k][128]
        __half hi = __float2half_rn(w);
        __half lo = __float2half_rn(w - __half2float(hi));
        g_wth[mat * 16384 + o * 128 + k] = hi;
        g_wtl[mat * 16384 + o * 128 + k] = lo;
    } else if (i < 4 * 16384 + 2 * 8192) {
        int j = i - 65536;
        int mat = 4 + (j >> 13), idx = j & 8191;
        const float* Ws2[2] = {W2l, W2r};
        float w = Ws2[mat - 4][idx];
        int k = idx >> 6, o = idx & 63;         // src W2[k][64]
        __half hi = __float2half_rn(w);
        __half lo = __float2half_rn(w - __half2float(hi));
        g_wth[mat * 16384 + o * 128 + k] = hi;
        g_wtl[mat * 16384 + o * 128 + k] = lo;
    }
}

__global__ void convert_count_k(const void* __restrict__ ei) {
    int i = blockIdx.x * blockDim.x + threadIdx.x;
    if (i >= ET) return;
    int s, d;
    if (i < NE) {
        if (g_is64) {
            s = (int)((const long long*)ei)[i];
            d = (int)((const long long*)ei)[NE + i];
        } else {
            s = ((const int*)ei)[i];
            d = ((const int*)ei)[NE + i];
        }
    } else {
        s = d = i - NE;                       // appended self loops
    }
    s = min(max(s, 0), NN - 1);               // defensive: never fault
    d = min(max(d, 0), NN - 1);
    g_src[i] = s;
    g_dst[i] = d;
    atomicAdd(&g_deg[d], 1);
}

__global__ void scan1_k() {
    __shared__ int sh[1024];
    int i = blockIdx.x * 1024 + threadIdx.x;
    int v = (i < NN) ? g_deg[i] : 0;
    sh[threadIdx.x] = v;
    __syncthreads();
    for (int off = 1; off < 1024; off <<= 1) {
        int t = (threadIdx.x >= off) ? sh[threadIdx.x - off] : 0;
        __syncthreads();
        sh[threadIdx.x] += t;
        __syncthreads();
    }
    if (i < NN) g_tmp[i] = sh[threadIdx.x];
    if (threadIdx.x == 1023) g_bsums[blockIdx.x] = sh[1023];
}

// fused scan2+scan3
__global__ void scan3_k() {
    __shared__ int pref[NB + 1];
    if (threadIdx.x == 0) {
        int acc = 0;
        for (int b = 0; b < NB; b++) { pref[b] = acc; acc += g_bsums[b]; }
    }
    __syncthreads();
    int i = blockIdx.x * blockDim.x + threadIdx.x;
    if (i < NN) {
        int incl = g_tmp[i] + pref[i >> 10];
        g_rowptr[i + 1] = incl;
        g_fill[i] = incl - g_deg[i];           // exclusive prefix = fill cursor
    }
    if (i == 0) g_rowptr[0] = 0;
}

__global__ void scatter_k() {
    int i = blockIdx.x * blockDim.x + threadIdx.x;
    if (i >= ET) return;
    int pos = atomicAdd(&g_fill[g_dst[i]], 1);
    g_esrc[pos] = g_src[i];
}

// ---------------- asymmetric dual tensor-core GEMM --------------------
// L side (hl, aggregated): fp16x3. R side (hr, score-only): plain fp16.
__device__ __forceinline__ void mma16(float* c, const unsigned* a,
                                      unsigned b0, unsigned b1) {
    asm volatile(
        "mma.sync.aligned.m16n8k16.row.col.f32.f16.f16.f32 "
        "{%0,%1,%2,%3}, {%4,%5,%6,%7}, {%8,%9}, {%0,%1,%2,%3};"
        : "+f"(c[0]), "+f"(c[1]), "+f"(c[2]), "+f"(c[3])
        : "r"(a[0]), "r"(a[1]), "r"(a[2]), "r"(a[3]), "r"(b0), "r"(b1));
}

__device__ __forceinline__ void cp16(unsigned dst, const void* src, int srcBytes) {
    asm volatile("cp.async.ca.shared.global [%0], [%1], 16, %2;"
                 :: "r"(dst), "l"(src), "r"(srcBytes));
}

__device__ __forceinline__ void split2(float x, float y, unsigned& hi, unsigned& lo) {
    __half2 h = __floats2half2_rn(x, y);
    __half2 l = __floats2half2_rn(x - __low2float(h), y - __high2float(h));
    hi = *reinterpret_cast<unsigned*>(&h);
    lo = *reinterpret_cast<unsigned*>(&l);
}

// B smem rows of 16 halves (2 x 16B chunks), chunk swizzled by row bit2.
__device__ __forceinline__ unsigned ldb(const __half* buf, int row, int u) {
    int idx = row * 8 + (u ^ (((row >> 2) & 1) << 2));
    return reinterpret_cast<const unsigned*>(buf)[idx];
}

// 3-stage cp.async pipeline, ONE __syncthreads per k-iteration.
__global__ __launch_bounds__(256, 2) void gemm_dual_k(
    const float* __restrict__ A,
    const __half* __restrict__ Blh, const __half* __restrict__ Bll,
    const __half* __restrict__ Brh,
    __half* __restrict__ Cl, float* __restrict__ Cr, int n, int oc)
{
    __shared__ float  As[3][BM * 16];                 // fp32 A, XOR-swizzled
    __shared__ __half Bsh[3][2][BN * 16];             // [stage][side] hi
    __shared__ __half Bsl[3][BN * 16];                // [stage] L-side lo

    const int tid = threadIdx.x;
    const int lane = tid & 31, wid = tid >> 5;
    const int wm = wid >> 1, wn = wid & 1;       // 4 x 2 warp grid
    const int gid = lane >> 2, tig = lane & 3;
    const int row0 = blockIdx.x * BM;
    const int col0 = blockIdx.y * BN;

    float acc[2][2][4][4];                        // [side][i][j][reg]
#pragma unroll
    for (int sd = 0; sd < 2; sd++)
#pragma unroll
        for (int i = 0; i < 2; i++)
#pragma unroll
            for (int j = 0; j < 4; j++)
#pragma unroll
                for (int r = 0; r < 4; r++) acc[sd][i][j][r] = 0.f;

    const int ar = tid >> 1, kof = (tid & 1) * 8;      // A: 2x16B per thread
    const int aswz = 4 * (ar & 3);
    const int aValid = (row0 + ar < n) ? 16 : 0;
    const int bt = tid & 127, bside = tid >> 7;        // B halves
    const int brr = bt >> 1, bcc = bt & 1;
    const int bOff = brr * 32 + 16 * (bcc ^ ((brr >> 2) & 1));  // bytes

    auto load_stage = [&](int st, int kk) {
        const float* srcA = A + (size_t)(row0 + ar) * 128 + kk + kof;
        cp16((unsigned)__cvta_generic_to_shared(&As[st][ar * 16 + (kof ^ aswz)]),
             srcA, aValid);
        cp16((unsigned)__cvta_generic_to_shared(&As[st][ar * 16 + ((kof + 4) ^ aswz)]),
             srcA + 4, aValid);
        if (bside == 0) {
            const __half* sh = Blh + (size_t)(col0 + brr) * 128 + kk + 8 * bcc;
            const __half* sl = Bll + (size_t)(col0 + brr) * 128 + kk + 8 * bcc;
            cp16((unsigned)__cvta_generic_to_shared(
                     reinterpret_cast<char*>(Bsh[st][0]) + bOff), sh, 16);
            cp16((unsigned)__cvta_generic_to_shared(
                     reinterpret_cast<char*>(Bsl[st]) + bOff), sl, 16);
        } else {
            const __half* sh = Brh + (size_t)(col0 + brr) * 128 + kk + 8 * bcc;
            cp16((unsigned)__cvta_generic_to_shared(
                     reinterpret_cast<char*>(Bsh[st][1]) + bOff), sh, 16);
        }
    };

    load_stage(0, 0);
    asm volatile("cp.async.commit_group;");
    load_stage(1, BK);
    asm volatile("cp.async.commit_group;");

    const int kp0 = 2 * tig;            // A k-pair base
#pragma unroll
    for (int it = 0; it < 8; it++) {
        const int buf = it % 3;
        if (it == 7) asm volatile("cp.async.wait_group 0;");
        else         asm volatile("cp.async.wait_group 1;");
        __syncthreads();   // stage `buf` ready; all warps done computing stage (it-1)%3

        unsigned ah[2][4], al[2][4];
#pragma unroll
        for (int i = 0; i < 2; i++) {
            const int m0 = wm * 32 + i * 16;
            const int r0 = m0 + gid, r1 = r0 + 8;
            const int s0 = 4 * (r0 & 3), s1 = 4 * (r1 & 3);
            float2 f0 = *reinterpret_cast<const float2*>(&As[buf][r0 * 16 + (kp0 ^ s0)]);
            float2 f1 = *reinterpret_cast<const float2*>(&As[buf][r1 * 16 + (kp0 ^ s1)]);
            float2 f2 = *reinterpret_cast<const float2*>(&As[buf][r0 * 16 + ((kp0 + 8) ^ s0)]);
            float2 f3 = *reinterpret_cast<const float2*>(&As[buf][r1 * 16 + ((kp0 + 8) ^ s1)]);
            split2(f0.x, f0.y, ah[i][0], al[i][0]);
            split2(f1.x, f1.y, ah[i][1], al[i][1]);
            split2(f2.x, f2.y, ah[i][2], al[i][2]);
            split2(f3.x, f3.y, ah[i][3], al[i][3]);
        }

#pragma unroll
        for (int j = 0; j < 4; j++) {
            const int c = wn * 32 + j * 8 + gid;
            unsigned bh0 = ldb(Bsh[buf][0], c, tig);
            unsigned bh1 = ldb(Bsh[buf][0], c, tig + 4);
            unsigned bl0 = ldb(Bsl[buf], c, tig);
            unsigned bl1 = ldb(Bsl[buf], c, tig + 4);
            unsigned rh0 = ldb(Bsh[buf][1], c, tig);
            unsigned rh1 = ldb(Bsh[buf][1], c, tig + 4);
#pragma unroll
            for (int i = 0; i < 2; i++) {
                mma16(acc[0][i][j], ah[i], bh0, bh1);   // L: x3
                mma16(acc[0][i][j], ah[i], bl0, bl1);
                mma16(acc[0][i][j], al[i], bh0, bh1);
                mma16(acc[1][i][j], ah[i], rh0, rh1);   // R: x1
            }
        }

        if (it + 2 < 8) {
            load_stage((it + 2) % 3, (it + 2) * BK);
            asm volatile("cp.async.commit_group;");
        }
    }

#pragma unroll
    for (int i = 0; i < 2; i++) {
        int rbase = row0 + wm * 32 + i * 16 + gid;
#pragma unroll
        for (int j = 0; j < 4; j++) {
            int c = col0 + wn * 32 + j * 8 + 2 * tig;
            if (rbase < n) {
                *reinterpret_cast<__half2*>(Cl + (size_t)rbase * oc + c) =
                    __floats2half2_rn(acc[0][i][j][0], acc[0][i][j][1]);
                *reinterpret_cast<float2*>(Cr + (size_t)rbase * oc + c) =
                    make_float2(acc[1][i][j][0], acc[1][i][j][1]);
            }
            if (rbase + 8 < n) {
                *reinterpret_cast<__half2*>(Cl + (size_t)(rbase + 8) * oc + c) =
                    __floats2half2_rn(acc[0][i][j][2], acc[0][i][j][3]);
                *reinterpret_cast<float2*>(Cr + (size_t)(rbase + 8) * oc + c) =
                    make_float2(acc[1][i][j][2], acc[1][i][j][3]);
            }
        }
    }
}

// ---------------- fused edge kernel: segment softmax + aggregate ----------
// One warp per destination node; self-loop score as softmax offset.
// Depth-1 software pipeline on batches of 4 edges; dual accumulator banks.
template <int H, int CH>
__global__ __launch_bounds__(256) void gat_edge(
    const __half* __restrict__ hl, const float* __restrict__ hr,
    const float* __restrict__ att, const float* __restrict__ bias,
    float* __restrict__ out)
{
    constexpr int V = CH / 32;
    const int w = (blockIdx.x * blockDim.x + threadIdx.x) >> 5;
    const int lane = threadIdx.x & 31;
    if (w >= NN) return;

    float attv[V], hrv[V];
#pragma unroll
    for (int v = 0; v < V; v++) attv[v] = att[lane * V + v];

    if (V == 4) {
        float4 t = __ldg(reinterpret_cast<const float4*>(hr) + w * 32 + lane);
        hrv[0] = t.x; hrv[1] = t.y; hrv[2] = t.z; hrv[3] = t.w;
    } else {
        float2 t = __ldg(reinterpret_cast<const float2*>(hr) + w * 32 + lane);
        hrv[0] = t.x; hrv[1] = t.y;
    }

    const uint2* hl2 = reinterpret_cast<const uint2*>(hl);
    const unsigned* hl1 = reinterpret_cast<const unsigned*>(hl);

    auto gatherraw = [&](int s) -> uint2 {
        if (V == 4) return __ldg(hl2 + s * 32 + lane);
        uint2 r; r.x = __ldg(hl1 + s * 32 + lane); r.y = 0; return r;
    };
    auto tof = [&](uint2 t, float* hv) {
        float2 f01 = __half22float2(*reinterpret_cast<__half2*>(&t.x));
        hv[0] = f01.x; hv[1] = f01.y;
        if (V == 4) {
            float2 f23 = __half22float2(*reinterpret_cast<__half2*>(&t.y));
            hv[2] = f23.x; hv[3] = f23.y;
        }
    };
    auto score = [&](const float* hv) {
        float p = 0.f;
#pragma unroll
        for (int v = 0; v < V; v++) {
            float t = hv[v] + hrv[v];
            t = (t > 0.f) ? t : 0.2f * t;          // LeakyReLU(0.2)
            p = fmaf(t, attv[v], p);
        }
#pragma unroll
        for (int off = (32 / H) >> 1; off > 0; off >>= 1)
            p += __shfl_xor_sync(0xffffffffu, p, off);
        return p;
    };

    float p_self;
    {
        float hs[V];
        tof(gatherraw(w), hs);
        p_self = score(hs);
    }

    float lsum0 = 0.f, lsum1 = 0.f;
    float acc0[V], acc1[V];
#pragma unroll
    for (int v = 0; v < V; v++) { acc0[v] = 0.f; acc1[v] = 0.f; }

    auto update = [&](uint2 raw, float (&accb)[V], float& lsumb) {
        float hv[V];
        tof(raw, hv);
        float p = score(hv);
        float ww = __expf(p - p_self);
        lsumb += ww;
#pragma unroll
        for (int v = 0; v < V; v++) accb[v] = fmaf(ww, hv[v], accb[v]);
    };

    const int e0 = g_rowptr[w], e1 = g_rowptr[w + 1];
    int e = e0;
    const int nfull = (e1 - e0) >> 2;

    uint2 cur0, cur1, cur2, cur3;
    if (nfull > 0) {
        int s0 = __ldg(&g_esrc[e]);
        int s1 = __ldg(&g_esrc[e + 1]);
        int s2 = __ldg(&g_esrc[e + 2]);
        int s3 = __ldg(&g_esrc[e + 3]);
        cur0 = gatherraw(s0); cur1 = gatherraw(s1);
        cur2 = gatherraw(s2); cur3 = gatherraw(s3);
    }
    for (int b = 0; b < nfull; b++) {
        uint2 n0, n1, n2, n3;
        const bool more = (b + 1 < nfull);
        if (more) {
            int s0 = __ldg(&g_esrc[e + 4]);
            int s1 = __ldg(&g_esrc[e + 5]);
            int s2 = __ldg(&g_esrc[e + 6]);
            int s3 = __ldg(&g_esrc[e + 7]);
            n0 = gatherraw(s0); n1 = gatherraw(s1);
            n2 = gatherraw(s2); n3 = gatherraw(s3);
        }
        update(cur0, acc0, lsum0);
        update(cur1, acc1, lsum1);
        update(cur2, acc0, lsum0);
        update(cur3, acc1, lsum1);
        if (more) { cur0 = n0; cur1 = n1; cur2 = n2; cur3 = n3; }
        e += 4;
    }
    for (; e < e1; e++) {
        update(gatherraw(__ldg(&g_esrc[e])), acc0, lsum0);
    }

    float inv = 1.f / (lsum0 + lsum1 + 1e-16f);
    if (V == 4) {
        float4 o;
        o.x = fmaxf(fmaf(acc0[0] + acc1[0], inv, bias[lane * 4 + 0]), 0.f);
        o.y = fmaxf(fmaf(acc0[1] + acc1[1], inv, bias[lane * 4 + 1]), 0.f);
        o.z = fmaxf(fmaf(acc0[2] + acc1[2], inv, bias[lane * 4 + 2]), 0.f);
        o.w = fmaxf(fmaf(acc0[3] + acc1[3], inv, bias[lane * 4 + 3]), 0.f);
        reinterpret_cast<float4*>(out)[w * 32 + lane] = o;
    } else {
        float2 o;
        o.x = fmaxf(fmaf(acc0[0] + acc1[0], inv, bias[lane * 2 + 0]), 0.f);
        o.y = fmaxf(fmaf(acc0[1] + acc1[1], inv, bias[lane * 2 + 1]), 0.f);
        reinterpret_cast<float2*>(out)[w * 32 + lane] = o;
    }
}

// ---------------- launch ----------------
extern "C" void kernel_launch(void* const* d_in, const int* in_sizes, int n_in,
                              void* d_out, int out_size)
{
    const float* x   = (const float*)d_in[0];
    const void*  ei  = d_in[1];
    const float *W0l = (const float*)d_in[2],  *W0r = (const float*)d_in[3];
    const float *a0  = (const float*)d_in[4],  *b0  = (const float*)d_in[5];
    const float *W1l = (const float*)d_in[6],  *W1r = (const float*)d_in[7];
    const float *a1  = (const float*)d_in[8],  *b1  = (const float*)d_in[9];
    const float *W2l = (const float*)d_in[10], *W2r = (const float*)d_in[11];
    const float *a2  = (const float*)d_in[12], *b2  = (const float*)d_in[13];
    float* out = (float*)d_out;

    void *p_hlh, *p_hr, *p_h, *p_wth, *p_wtl;
    cudaGetSymbolAddress(&p_hlh, g_hlh);
    cudaGetSymbolAddress(&p_hr, g_hr);
    cudaGetSymbolAddress(&p_h, g_h);
    cudaGetSymbolAddress(&p_wth, g_wth);
    cudaGetSymbolAddress(&p_wtl, g_wtl);
    __half* hl  = (__half*)p_hlh;
    float*  hr  = (float*)p_hr;
    float*  h   = (float*)p_h;
    __half* wth = (__half*)p_wth;
    __half* wtl = (__half*)p_wtl;

    const int eb = (ET + 255) / 256;
    const dim3 gg((NN + BM - 1) / BM, 2);
    const dim3 gg2((NN + BM - 1) / BM, 1);
    const int egrid = (NN * 32 + 255) / 256;

    zero_detect_k<<<(NN + 1023) / 1024, 1024>>>((const int*)ei,
        W0l, W0r, W1l, W1r, W2l, W2r);                               // 1
    convert_count_k<<<eb, 256>>>(ei);                                // 2
    scan1_k<<<NB, 1024>>>();                                         // 3
    gemm_dual_k<<<gg, 256>>>(x, wth, wtl, wth + 16384,
                             hl, hr, NN, 128);                       // 4 <- profiled
    scan3_k<<<(NN + 255) / 256, 256>>>();                            // 5
    scatter_k<<<eb, 256>>>();                                        // 6
    gat_edge<4, 128><<<egrid, 256>>>(hl, hr, a0, b0, h);             // 7
    gemm_dual_k<<<gg, 256>>>(h, wth + 2 * 16384, wtl + 2 * 16384,
                             wth + 3 * 16384, hl, hr, NN, 128);      // 8
    gat_edge<4, 128><<<egrid, 256>>>(hl, hr, a1, b1, h);             // 9
    gemm_dual_k<<<gg2, 256>>>(h, wth + 4 * 16384, wtl + 4 * 16384,
                              wth + 5 * 16384, hl, hr, NN, 64);      // 10
    gat_edge<1, 64><<<egrid, 256>>>(hl, hr, a2, b2, out);            // 11
}

// round 12
// speedup vs baseline: 1.0561x; 1.0561x over previous
#include <cuda_runtime.h>
#include <cuda_fp16.h>
#include <math.h>

#define NN 100000
#define NE 1600000
#define ET 1700000          // NE + NN self loops
#define NB 98               // ceil(NN/1024)

// GEMM tiling
#define BM 128
#define BN 64
#define BK 16

// ---------------- static scratch (no allocations allowed) ----------------
__device__ __align__(256) __half g_hlh[NN * 128];   // hl fp16 (edge gather)
__device__ __align__(256) float  g_hr[NN * 128];
__device__ __align__(256) float  g_h [NN * 128];
__device__ __align__(256) __half g_wth[6 * 16384];  // W^T [oc][128], fp16 hi
__device__ __align__(256) __half g_wtl[6 * 16384];  // W^T lo residual
__device__ int g_deg[NN];
__device__ int g_tmp[NN];
__device__ int g_rowptr[NN + 1];
__device__ int g_fill[NN];
__device__ int g_esrc[ET];
__device__ int g_src[ET];
__device__ int g_dst[ET];
__device__ int g_bsums[128];
__device__ int g_is64;

// ---------------- ingestion + CSR + W convert ----------------
__global__ void zero_detect_k(const int* __restrict__ ei32,
                              const float* __restrict__ W0l, const float* __restrict__ W0r,
                              const float* __restrict__ W1l, const float* __restrict__ W1r,
                              const float* __restrict__ W2l, const float* __restrict__ W2r) {
    int i = blockIdx.x * blockDim.x + threadIdx.x;
    if (i < NN) g_deg[i] = 0;
    if (i == 0) {
        int acc = 0;
        for (int j = 0; j < 1024; j++) acc |= ei32[2 * j + 1];
        g_is64 = (acc == 0) ? 1 : 0;   // int64 little-endian => high words all 0
    }
    // W transpose + fp16 hi/lo split: Wt[oc][128] so k runs contiguous
    if (i < 4 * 16384) {
        int mat = i >> 14, idx = i & 16383;
        const float* Ws[4] = {W0l, W0r, W1l, W1r};
        float w = Ws[mat][idx];
        int k = idx >> 7, o = idx & 127;        // src W[k][128]
        __half hi = __float2half_rn(w);
        __half lo = __float2half_rn(w - __half2float(hi));
        g_wth[mat * 16384 + o * 128 + k] = hi;
        g_wtl[mat * 16384 + o * 128 + k] = lo;
    } else if (i < 4 * 16384 + 2 * 8192) {
        int j = i - 65536;
        int mat = 4 + (j >> 13), idx = j & 8191;
        const float* Ws2[2] = {W2l, W2r};
        float w = Ws2[mat - 4][idx];
        int k = idx >> 6, o = idx & 63;         // src W2[k][64]
        __half hi = __float2half_rn(w);
        __half lo = __float2half_rn(w - __half2float(hi));
        g_wth[mat * 16384 + o * 128 + k] = hi;
        g_wtl[mat * 16384 + o * 128 + k] = lo;
    }
}

__global__ void convert_count_k(const void* __restrict__ ei) {
    int i = blockIdx.x * blockDim.x + threadIdx.x;
    if (i >= ET) return;
    int s, d;
    if (i < NE) {
        if (g_is64) {
            s = (int)((const long long*)ei)[i];
            d = (int)((const long long*)ei)[NE + i];
        } else {
            s = ((const int*)ei)[i];
            d = ((const int*)ei)[NE + i];
        }
    } else {
        s = d = i - NE;                       // appended self loops
    }
    s = min(max(s, 0), NN - 1);               // defensive: never fault
    d = min(max(d, 0), NN - 1);
    g_src[i] = s;
    g_dst[i] = d;
    atomicAdd(&g_deg[d], 1);
}

__global__ void scan1_k() {
    __shared__ int sh[1024];
    int i = blockIdx.x * 1024 + threadIdx.x;
    int v = (i < NN) ? g_deg[i] : 0;
    sh[threadIdx.x] = v;
    __syncthreads();
    for (int off = 1; off < 1024; off <<= 1) {
        int t = (threadIdx.x >= off) ? sh[threadIdx.x - off] : 0;
        __syncthreads();
        sh[threadIdx.x] += t;
        __syncthreads();
    }
    if (i < NN) g_tmp[i] = sh[threadIdx.x];
    if (threadIdx.x == 1023) g_bsums[blockIdx.x] = sh[1023];
}

// fused scan2+scan3
__global__ void scan3_k() {
    __shared__ int pref[NB + 1];
    if (threadIdx.x == 0) {
        int acc = 0;
        for (int b = 0; b < NB; b++) { pref[b] = acc; acc += g_bsums[b]; }
    }
    __syncthreads();
    int i = blockIdx.x * blockDim.x + threadIdx.x;
    if (i < NN) {
        int incl = g_tmp[i] + pref[i >> 10];
        g_rowptr[i + 1] = incl;
        g_fill[i] = incl - g_deg[i];           // exclusive prefix = fill cursor
    }
    if (i == 0) g_rowptr[0] = 0;
}

__global__ void scatter_k() {
    int i = blockIdx.x * blockDim.x + threadIdx.x;
    if (i >= ET) return;
    int pos = atomicAdd(&g_fill[g_dst[i]], 1);
    g_esrc[pos] = g_src[i];
}

// ---------------- asymmetric dual tensor-core GEMM --------------------
// L side (hl, aggregated): fp16x3. R side (hr, score-only): plain fp16.
__device__ __forceinline__ void mma16(float* c, const unsigned* a,
                                      unsigned b0, unsigned b1) {
    asm volatile(
        "mma.sync.aligned.m16n8k16.row.col.f32.f16.f16.f32 "
        "{%0,%1,%2,%3}, {%4,%5,%6,%7}, {%8,%9}, {%0,%1,%2,%3};"
        : "+f"(c[0]), "+f"(c[1]), "+f"(c[2]), "+f"(c[3])
        : "r"(a[0]), "r"(a[1]), "r"(a[2]), "r"(a[3]), "r"(b0), "r"(b1));
}

__device__ __forceinline__ void cp16(unsigned dst, const void* src, int srcBytes) {
    asm volatile("cp.async.ca.shared.global [%0], [%1], 16, %2;"
                 :: "r"(dst), "l"(src), "r"(srcBytes));
}

__device__ __forceinline__ void split2(float x, float y, unsigned& hi, unsigned& lo) {
    __half2 h = __floats2half2_rn(x, y);
    __half2 l = __floats2half2_rn(x - __low2float(h), y - __high2float(h));
    hi = *reinterpret_cast<unsigned*>(&h);
    lo = *reinterpret_cast<unsigned*>(&l);
}

// B smem rows of 16 halves (2 x 16B chunks), chunk swizzled by row bit2.
__device__ __forceinline__ unsigned ldb(const __half* buf, int row, int u) {
    int idx = row * 8 + (u ^ (((row >> 2) & 1) << 2));
    return reinterpret_cast<const unsigned*>(buf)[idx];
}

// 3-stage cp.async pipeline, ONE __syncthreads per k-iteration.
__global__ __launch_bounds__(256, 2) void gemm_dual_k(
    const float* __restrict__ A,
    const __half* __restrict__ Blh, const __half* __restrict__ Bll,
    const __half* __restrict__ Brh,
    __half* __restrict__ Cl, float* __restrict__ Cr, int n, int oc)
{
    __shared__ float  As[3][BM * 16];                 // fp32 A, XOR-swizzled
    __shared__ __half Bsh[3][2][BN * 16];             // [stage][side] hi
    __shared__ __half Bsl[3][BN * 16];                // [stage] L-side lo

    const int tid = threadIdx.x;
    const int lane = tid & 31, wid = tid >> 5;
    const int wm = wid >> 1, wn = wid & 1;       // 4 x 2 warp grid
    const int gid = lane >> 2, tig = lane & 3;
    const int row0 = blockIdx.x * BM;
    const int col0 = blockIdx.y * BN;

    float acc[2][2][4][4];                        // [side][i][j][reg]
#pragma unroll
    for (int sd = 0; sd < 2; sd++)
#pragma unroll
        for (int i = 0; i < 2; i++)
#pragma unroll
            for (int j = 0; j < 4; j++)
#pragma unroll
                for (int r = 0; r < 4; r++) acc[sd][i][j][r] = 0.f;

    const int ar = tid >> 1, kof = (tid & 1) * 8;      // A: 2x16B per thread
    const int aswz = 4 * (ar & 3);
    const int aValid = (row0 + ar < n) ? 16 : 0;
    const int bt = tid & 127, bside = tid >> 7;        // B halves
    const int brr = bt >> 1, bcc = bt & 1;
    const int bOff = brr * 32 + 16 * (bcc ^ ((brr >> 2) & 1));  // bytes

    auto load_stage = [&](int st, int kk) {
        const float* srcA = A + (size_t)(row0 + ar) * 128 + kk + kof;
        cp16((unsigned)__cvta_generic_to_shared(&As[st][ar * 16 + (kof ^ aswz)]),
             srcA, aValid);
        cp16((unsigned)__cvta_generic_to_shared(&As[st][ar * 16 + ((kof + 4) ^ aswz)]),
             srcA + 4, aValid);
        if (bside == 0) {
            const __half* sh = Blh + (size_t)(col0 + brr) * 128 + kk + 8 * bcc;
            const __half* sl = Bll + (size_t)(col0 + brr) * 128 + kk + 8 * bcc;
            cp16((unsigned)__cvta_generic_to_shared(
                     reinterpret_cast<char*>(Bsh[st][0]) + bOff), sh, 16);
            cp16((unsigned)__cvta_generic_to_shared(
                     reinterpret_cast<char*>(Bsl[st]) + bOff), sl, 16);
        } else {
            const __half* sh = Brh + (size_t)(col0 + brr) * 128 + kk + 8 * bcc;
            cp16((unsigned)__cvta_generic_to_shared(
                     reinterpret_cast<char*>(Bsh[st][1]) + bOff), sh, 16);
        }
    };

    load_stage(0, 0);
    asm volatile("cp.async.commit_group;");
    load_stage(1, BK);
    asm volatile("cp.async.commit_group;");

    const int kp0 = 2 * tig;            // A k-pair base
#pragma unroll
    for (int it = 0; it < 8; it++) {
        const int buf = it % 3;
        if (it == 7) asm volatile("cp.async.wait_group 0;");
        else         asm volatile("cp.async.wait_group 1;");
        __syncthreads();   // stage `buf` ready; all warps done computing stage (it-1)%3

        unsigned ah[2][4], al[2][4];
#pragma unroll
        for (int i = 0; i < 2; i++) {
            const int m0 = wm * 32 + i * 16;
            const int r0 = m0 + gid, r1 = r0 + 8;
            const int s0 = 4 * (r0 & 3), s1 = 4 * (r1 & 3);
            float2 f0 = *reinterpret_cast<const float2*>(&As[buf][r0 * 16 + (kp0 ^ s0)]);
            float2 f1 = *reinterpret_cast<const float2*>(&As[buf][r1 * 16 + (kp0 ^ s1)]);
            float2 f2 = *reinterpret_cast<const float2*>(&As[buf][r0 * 16 + ((kp0 + 8) ^ s0)]);
            float2 f3 = *reinterpret_cast<const float2*>(&As[buf][r1 * 16 + ((kp0 + 8) ^ s1)]);
            split2(f0.x, f0.y, ah[i][0], al[i][0]);
            split2(f1.x, f1.y, ah[i][1], al[i][1]);
            split2(f2.x, f2.y, ah[i][2], al[i][2]);
            split2(f3.x, f3.y, ah[i][3], al[i][3]);
        }

#pragma unroll
        for (int j = 0; j < 4; j++) {
            const int c = wn * 32 + j * 8 + gid;
            unsigned bh0 = ldb(Bsh[buf][0], c, tig);
            unsigned bh1 = ldb(Bsh[buf][0], c, tig + 4);
            unsigned bl0 = ldb(Bsl[buf], c, tig);
            unsigned bl1 = ldb(Bsl[buf], c, tig + 4);
            unsigned rh0 = ldb(Bsh[buf][1], c, tig);
            unsigned rh1 = ldb(Bsh[buf][1], c, tig + 4);
#pragma unroll
            for (int i = 0; i < 2; i++) {
                mma16(acc[0][i][j], ah[i], bh0, bh1);   // L: x3
                mma16(acc[0][i][j], ah[i], bl0, bl1);
                mma16(acc[0][i][j], al[i], bh0, bh1);
                mma16(acc[1][i][j], ah[i], rh0, rh1);   // R: x1
            }
        }

        if (it + 2 < 8) {
            load_stage((it + 2) % 3, (it + 2) * BK);
            asm volatile("cp.async.commit_group;");
        }
    }

#pragma unroll
    for (int i = 0; i < 2; i++) {
        int rbase = row0 + wm * 32 + i * 16 + gid;
#pragma unroll
        for (int j = 0; j < 4; j++) {
            int c = col0 + wn * 32 + j * 8 + 2 * tig;
            if (rbase < n) {
                *reinterpret_cast<__half2*>(Cl + (size_t)rbase * oc + c) =
                    __floats2half2_rn(acc[0][i][j][0], acc[0][i][j][1]);
                *reinterpret_cast<float2*>(Cr + (size_t)rbase * oc + c) =
                    make_float2(acc[1][i][j][0], acc[1][i][j][1]);
            }
            if (rbase + 8 < n) {
                *reinterpret_cast<__half2*>(Cl + (size_t)(rbase + 8) * oc + c) =
                    __floats2half2_rn(acc[0][i][j][2], acc[0][i][j][3]);
                *reinterpret_cast<float2*>(Cr + (size_t)(rbase + 8) * oc + c) =
                    make_float2(acc[1][i][j][2], acc[1][i][j][3]);
            }
        }
    }
}

// ---------------- fused edge kernel: segment softmax + aggregate ----------
// One warp per destination node; self-loop score as softmax offset.
// Straight batch-of-4 gathers (4-deep MLP) + dual accumulator banks.
template <int H, int CH>
__global__ __launch_bounds__(256) void gat_edge(
    const __half* __restrict__ hl, const float* __restrict__ hr,
    const float* __restrict__ att, const float* __restrict__ bias,
    float* __restrict__ out)
{
    constexpr int V = CH / 32;
    const int w = (blockIdx.x * blockDim.x + threadIdx.x) >> 5;
    const int lane = threadIdx.x & 31;
    if (w >= NN) return;

    float attv[V], hrv[V];
#pragma unroll
    for (int v = 0; v < V; v++) attv[v] = att[lane * V + v];

    if (V == 4) {
        float4 t = __ldg(reinterpret_cast<const float4*>(hr) + w * 32 + lane);
        hrv[0] = t.x; hrv[1] = t.y; hrv[2] = t.z; hrv[3] = t.w;
    } else {
        float2 t = __ldg(reinterpret_cast<const float2*>(hr) + w * 32 + lane);
        hrv[0] = t.x; hrv[1] = t.y;
    }

    auto gather = [&](int s, float* hv) {
        if (V == 4) {
            uint2 t = __ldg(reinterpret_cast<const uint2*>(hl) + s * 32 + lane);
            float2 f01 = __half22float2(*reinterpret_cast<__half2*>(&t.x));
            float2 f23 = __half22float2(*reinterpret_cast<__half2*>(&t.y));
            hv[0] = f01.x; hv[1] = f01.y; hv[2] = f23.x; hv[3] = f23.y;
        } else {
            unsigned t = __ldg(reinterpret_cast<const unsigned*>(hl) + s * 32 + lane);
            float2 f = __half22float2(*reinterpret_cast<__half2*>(&t));
            hv[0] = f.x; hv[1] = f.y;
        }
    };

    auto score = [&](const float* hv) {
        float p = 0.f;
#pragma unroll
        for (int v = 0; v < V; v++) {
            float t = hv[v] + hrv[v];
            t = (t > 0.f) ? t : 0.2f * t;          // LeakyReLU(0.2)
            p = fmaf(t, attv[v], p);
        }
#pragma unroll
        for (int off = (32 / H) >> 1; off > 0; off >>= 1)
            p += __shfl_xor_sync(0xffffffffu, p, off);
        return p;
    };

    float p_self;
    {
        float hs[V];
        gather(w, hs);
        p_self = score(hs);
    }

    float lsum0 = 0.f, lsum1 = 0.f;
    float acc0[V], acc1[V];
#pragma unroll
    for (int v = 0; v < V; v++) { acc0[v] = 0.f; acc1[v] = 0.f; }

    auto update = [&](const float* hv, float (&accb)[V], float& lsumb) {
        float p = score(hv);
        float ww = __expf(p - p_self);
        lsumb += ww;
#pragma unroll
        for (int v = 0; v < V; v++) accb[v] = fmaf(ww, hv[v], accb[v]);
    };

    const int e0 = g_rowptr[w], e1 = g_rowptr[w + 1];
    int e = e0;
    for (; e + 4 <= e1; e += 4) {
        int s0 = __ldg(&g_esrc[e]);
        int s1 = __ldg(&g_esrc[e + 1]);
        int s2 = __ldg(&g_esrc[e + 2]);
        int s3 = __ldg(&g_esrc[e + 3]);
        float hv0[V], hv1[V], hv2[V], hv3[V];
        gather(s0, hv0); gather(s1, hv1); gather(s2, hv2); gather(s3, hv3);
        update(hv0, acc0, lsum0);
        update(hv1, acc1, lsum1);
        update(hv2, acc0, lsum0);
        update(hv3, acc1, lsum1);
    }
    for (; e < e1; e++) {
        float hv[V];
        gather(__ldg(&g_esrc[e]), hv);
        update(hv, acc0, lsum0);
    }

    float inv = 1.f / (lsum0 + lsum1 + 1e-16f);
    if (V == 4) {
        float4 o;
        o.x = fmaxf(fmaf(acc0[0] + acc1[0], inv, bias[lane * 4 + 0]), 0.f);
        o.y = fmaxf(fmaf(acc0[1] + acc1[1], inv, bias[lane * 4 + 1]), 0.f);
        o.z = fmaxf(fmaf(acc0[2] + acc1[2], inv, bias[lane * 4 + 2]), 0.f);
        o.w = fmaxf(fmaf(acc0[3] + acc1[3], inv, bias[lane * 4 + 3]), 0.f);
        reinterpret_cast<float4*>(out)[w * 32 + lane] = o;
    } else {
        float2 o;
        o.x = fmaxf(fmaf(acc0[0] + acc1[0], inv, bias[lane * 2 + 0]), 0.f);
        o.y = fmaxf(fmaf(acc0[1] + acc1[1], inv, bias[lane * 2 + 1]), 0.f);
        reinterpret_cast<float2*>(out)[w * 32 + lane] = o;
    }
}

// ---------------- launch ----------------
extern "C" void kernel_launch(void* const* d_in, const int* in_sizes, int n_in,
                              void* d_out, int out_size)
{
    const float* x   = (const float*)d_in[0];
    const void*  ei  = d_in[1];
    const float *W0l = (const float*)d_in[2],  *W0r = (const float*)d_in[3];
    const float *a0  = (const float*)d_in[4],  *b0  = (const float*)d_in[5];
    const float *W1l = (const float*)d_in[6],  *W1r = (const float*)d_in[7];
    const float *a1  = (const float*)d_in[8],  *b1  = (const float*)d_in[9];
    const float *W2l = (const float*)d_in[10], *W2r = (const float*)d_in[11];
    const float *a2  = (const float*)d_in[12], *b2  = (const float*)d_in[13];
    float* out = (float*)d_out;

    void *p_hlh, *p_hr, *p_h, *p_wth, *p_wtl;
    cudaGetSymbolAddress(&p_hlh, g_hlh);
    cudaGetSymbolAddress(&p_hr, g_hr);
    cudaGetSymbolAddress(&p_h, g_h);
    cudaGetSymbolAddress(&p_wth, g_wth);
    cudaGetSymbolAddress(&p_wtl, g_wtl);
    __half* hl  = (__half*)p_hlh;
    float*  hr  = (float*)p_hr;
    float*  h   = (float*)p_h;
    __half* wth = (__half*)p_wth;
    __half* wtl = (__half*)p_wtl;

    const int eb = (ET + 255) / 256;
    const dim3 gg((NN + BM - 1) / BM, 2);
    const dim3 gg2((NN + BM - 1) / BM, 1);
    const int egrid = (NN * 32 + 255) / 256;

    zero_detect_k<<<(NN + 1023) / 1024, 1024>>>((const int*)ei,
        W0l, W0r, W1l, W1r, W2l, W2r);                               // 1
    convert_count_k<<<eb, 256>>>(ei);                                // 2
    scan1_k<<<NB, 1024>>>();                                         // 3
    gemm_dual_k<<<gg, 256>>>(x, wth, wtl, wth + 16384,
                             hl, hr, NN, 128);                       // 4 <- profiled
    scan3_k<<<(NN + 255) / 256, 256>>>();                            // 5
    scatter_k<<<eb, 256>>>();                                        // 6
    gat_edge<4, 128><<<egrid, 256>>>(hl, hr, a0, b0, h);             // 7
    gemm_dual_k<<<gg, 256>>>(h, wth + 2 * 16384, wtl + 2 * 16384,
                             wth + 3 * 16384, hl, hr, NN, 128);      // 8
    gat_edge<4, 128><<<egrid, 256>>>(hl, hr, a1, b1, h);             // 9
    gemm_dual_k<<<gg2, 256>>>(h, wth + 4 * 16384, wtl + 4 * 16384,
                              wth + 5 * 16384, hl, hr, NN, 64);      // 10
    gat_edge<1, 64><<<egrid, 256>>>(hl, hr, a2, b2, out);            // 11
}

// round 13
// speedup vs baseline: 1.0979x; 1.0396x over previous
#include <cuda_runtime.h>
#include <cuda_fp16.h>
#include <math.h>

#define NN 100000
#define NE 1600000
#define ET 1700000          // NE + NN self loops
#define NB 98               // ceil(NN/1024)

// GEMM tiling
#define BM 128
#define BN 64
#define BK 16

#define GTILES 1564         // 782 x 2 tiles for the 128-col GEMM
#define CONVB 6641          // ceil(ET/256) convert blocks
#define FUSEB (GTILES * 5)  // gemm blocks sit at bx%5==0, bx<FUSEB

// ---------------- static scratch (no allocations allowed) ----------------
__device__ __align__(256) __half g_hlh[NN * 128];   // hl fp16 (edge gather)
__device__ __align__(256) float  g_hr[NN * 128];
__device__ __align__(256) float  g_h [NN * 128];
__device__ __align__(256) __half g_wth[6 * 16384];  // W^T [oc][128], fp16 hi
__device__ __align__(256) __half g_wtl[6 * 16384];  // W^T lo residual
__device__ int g_deg[NN];
__device__ int g_tmp[NN];
__device__ int g_rowptr[NN + 1];
__device__ int g_fill[NN];
__device__ int g_esrc[ET];
__device__ int g_src[ET];
__device__ int g_dst[ET];
__device__ int g_bsums[128];
__device__ int g_is64;

// ---------------- setup: zero deg, detect dtype (parallel), convert W ----
__global__ void zero_detect_k(const int* __restrict__ ei32,
                              const float* __restrict__ W0l, const float* __restrict__ W0r,
                              const float* __restrict__ W1l, const float* __restrict__ W1r,
                              const float* __restrict__ W2l, const float* __restrict__ W2r) {
    int i = blockIdx.x * blockDim.x + threadIdx.x;
    if (i < NN) g_deg[i] = 0;
    // parallel dtype detect: one warp, 32 loads/lane + OR-reduce
    if (blockIdx.x == 0 && threadIdx.x < 32) {
        int acc = 0;
        for (int j = threadIdx.x; j < 1024; j += 32) acc |= ei32[2 * j + 1];
#pragma unroll
        for (int off = 16; off > 0; off >>= 1)
            acc |= __shfl_xor_sync(0xffffffffu, acc, off);
        if (threadIdx.x == 0) g_is64 = (acc == 0) ? 1 : 0;
    }
    // W transpose + fp16 hi/lo split: Wt[oc][128] so k runs contiguous
    if (i < 4 * 16384) {
        int mat = i >> 14, idx = i & 16383;
        const float* Ws[4] = {W0l, W0r, W1l, W1r};
        float w = Ws[mat][idx];
        int k = idx >> 7, o = idx & 127;        // src W[k][128]
        __half hi = __float2half_rn(w);
        __half lo = __float2half_rn(w - __half2float(hi));
        g_wth[mat * 16384 + o * 128 + k] = hi;
        g_wtl[mat * 16384 + o * 128 + k] = lo;
    } else if (i < 4 * 16384 + 2 * 8192) {
        int j = i - 65536;
        int mat = 4 + (j >> 13), idx = j & 8191;
        const float* Ws2[2] = {W2l, W2r};
        float w = Ws2[mat - 4][idx];
        int k = idx >> 6, o = idx & 63;         // src W2[k][64]
        __half hi = __float2half_rn(w);
        __half lo = __float2half_rn(w - __half2float(hi));
        g_wth[mat * 16384 + o * 128 + k] = hi;
        g_wtl[mat * 16384 + o * 128 + k] = lo;
    }
}

__global__ void scan1_k() {
    __shared__ int sh[1024];
    int i = blockIdx.x * 1024 + threadIdx.x;
    int v = (i < NN) ? g_deg[i] : 0;
    sh[threadIdx.x] = v;
    __syncthreads();
    for (int off = 1; off < 1024; off <<= 1) {
        int t = (threadIdx.x >= off) ? sh[threadIdx.x - off] : 0;
        __syncthreads();
        sh[threadIdx.x] += t;
        __syncthreads();
    }
    if (i < NN) g_tmp[i] = sh[threadIdx.x];
    if (threadIdx.x == 1023) g_bsums[blockIdx.x] = sh[1023];
}

// fused scan2+scan3
__global__ void scan3_k() {
    __shared__ int pref[NB + 1];
    if (threadIdx.x == 0) {
        int acc = 0;
        for (int b = 0; b < NB; b++) { pref[b] = acc; acc += g_bsums[b]; }
    }
    __syncthreads();
    int i = blockIdx.x * blockDim.x + threadIdx.x;
    if (i < NN) {
        int incl = g_tmp[i] + pref[i >> 10];
        g_rowptr[i + 1] = incl;
        g_fill[i] = incl - g_deg[i];           // exclusive prefix = fill cursor
    }
    if (i == 0) g_rowptr[0] = 0;
}

__global__ void scatter_k() {
    int i = blockIdx.x * blockDim.x + threadIdx.x;
    if (i >= ET) return;
    int pos = atomicAdd(&g_fill[g_dst[i]], 1);
    g_esrc[pos] = g_src[i];
}

// ---------------- asymmetric dual tensor-core GEMM body -------------------
// L side (hl, aggregated): fp16x3. R side (hr, score-only): plain fp16.
__device__ __forceinline__ void mma16(float* c, const unsigned* a,
                                      unsigned b0, unsigned b1) {
    asm volatile(
        "mma.sync.aligned.m16n8k16.row.col.f32.f16.f16.f32 "
        "{%0,%1,%2,%3}, {%4,%5,%6,%7}, {%8,%9}, {%0,%1,%2,%3};"
        : "+f"(c[0]), "+f"(c[1]), "+f"(c[2]), "+f"(c[3])
        : "r"(a[0]), "r"(a[1]), "r"(a[2]), "r"(a[3]), "r"(b0), "r"(b1));
}

__device__ __forceinline__ void cp16(unsigned dst, const void* src, int srcBytes) {
    asm volatile("cp.async.ca.shared.global [%0], [%1], 16, %2;"
                 :: "r"(dst), "l"(src), "r"(srcBytes));
}

__device__ __forceinline__ void split2(float x, float y, unsigned& hi, unsigned& lo) {
    __half2 h = __floats2half2_rn(x, y);
    __half2 l = __floats2half2_rn(x - __low2float(h), y - __high2float(h));
    hi = *reinterpret_cast<unsigned*>(&h);
    lo = *reinterpret_cast<unsigned*>(&l);
}

// B smem rows of 16 halves (2 x 16B chunks), chunk swizzled by row bit2.
__device__ __forceinline__ unsigned ldb(const __half* buf, int row, int u) {
    int idx = row * 8 + (u ^ (((row >> 2) & 1) << 2));
    return reinterpret_cast<const unsigned*>(buf)[idx];
}

// 3-stage cp.async pipeline, ONE __syncthreads per k-iteration.
__device__ __forceinline__ void gemm_tile_body(
    const float* __restrict__ A,
    const __half* __restrict__ Blh, const __half* __restrict__ Bll,
    const __half* __restrict__ Brh,
    __half* __restrict__ Cl, float* __restrict__ Cr,
    int n, int oc, int row0, int col0)
{
    __shared__ float  As[3][BM * 16];                 // fp32 A, XOR-swizzled
    __shared__ __half Bsh[3][2][BN * 16];             // [stage][side] hi
    __shared__ __half Bsl[3][BN * 16];                // [stage] L-side lo

    const int tid = threadIdx.x;
    const int lane = tid & 31, wid = tid >> 5;
    const int wm = wid >> 1, wn = wid & 1;       // 4 x 2 warp grid
    const int gid = lane >> 2, tig = lane & 3;

    float acc[2][2][4][4];                        // [side][i][j][reg]
#pragma unroll
    for (int sd = 0; sd < 2; sd++)
#pragma unroll
        for (int i = 0; i < 2; i++)
#pragma unroll
            for (int j = 0; j < 4; j++)
#pragma unroll
                for (int r = 0; r < 4; r++) acc[sd][i][j][r] = 0.f;

    const int ar = tid >> 1, kof = (tid & 1) * 8;      // A: 2x16B per thread
    const int aswz = 4 * (ar & 3);
    const int aValid = (row0 + ar < n) ? 16 : 0;
    const int bt = tid & 127, bside = tid >> 7;        // B halves
    const int brr = bt >> 1, bcc = bt & 1;
    const int bOff = brr * 32 + 16 * (bcc ^ ((brr >> 2) & 1));  // bytes

    auto load_stage = [&](int st, int kk) {
        const float* srcA = A + (size_t)(row0 + ar) * 128 + kk + kof;
        cp16((unsigned)__cvta_generic_to_shared(&As[st][ar * 16 + (kof ^ aswz)]),
             srcA, aValid);
        cp16((unsigned)__cvta_generic_to_shared(&As[st][ar * 16 + ((kof + 4) ^ aswz)]),
             srcA + 4, aValid);
        if (bside == 0) {
            const __half* sh = Blh + (size_t)(col0 + brr) * 128 + kk + 8 * bcc;
            const __half* sl = Bll + (size_t)(col0 + brr) * 128 + kk + 8 * bcc;
            cp16((unsigned)__cvta_generic_to_shared(
                     reinterpret_cast<char*>(Bsh[st][0]) + bOff), sh, 16);
            cp16((unsigned)__cvta_generic_to_shared(
                     reinterpret_cast<char*>(Bsl[st]) + bOff), sl, 16);
        } else {
            const __half* sh = Brh + (size_t)(col0 + brr) * 128 + kk + 8 * bcc;
            cp16((unsigned)__cvta_generic_to_shared(
                     reinterpret_cast<char*>(Bsh[st][1]) + bOff), sh, 16);
        }
    };

    load_stage(0, 0);
    asm volatile("cp.async.commit_group;");
    load_stage(1, BK);
    asm volatile("cp.async.commit_group;");

    const int kp0 = 2 * tig;            // A k-pair base
#pragma unroll
    for (int it = 0; it < 8; it++) {
        const int buf = it % 3;
        if (it == 7) asm volatile("cp.async.wait_group 0;");
        else         asm volatile("cp.async.wait_group 1;");
        __syncthreads();   // stage `buf` ready; all warps done with stage (it-1)%3

        unsigned ah[2][4], al[2][4];
#pragma unroll
        for (int i = 0; i < 2; i++) {
            const int m0 = wm * 32 + i * 16;
            const int r0 = m0 + gid, r1 = r0 + 8;
            const int s0 = 4 * (r0 & 3), s1 = 4 * (r1 & 3);
            float2 f0 = *reinterpret_cast<const float2*>(&As[buf][r0 * 16 + (kp0 ^ s0)]);
            float2 f1 = *reinterpret_cast<const float2*>(&As[buf][r1 * 16 + (kp0 ^ s1)]);
            float2 f2 = *reinterpret_cast<const float2*>(&As[buf][r0 * 16 + ((kp0 + 8) ^ s0)]);
            float2 f3 = *reinterpret_cast<const float2*>(&As[buf][r1 * 16 + ((kp0 + 8) ^ s1)]);
            split2(f0.x, f0.y, ah[i][0], al[i][0]);
            split2(f1.x, f1.y, ah[i][1], al[i][1]);
            split2(f2.x, f2.y, ah[i][2], al[i][2]);
            split2(f3.x, f3.y, ah[i][3], al[i][3]);
        }

#pragma unroll
        for (int j = 0; j < 4; j++) {
            const int c = wn * 32 + j * 8 + gid;
            unsigned bh0 = ldb(Bsh[buf][0], c, tig);
            unsigned bh1 = ldb(Bsh[buf][0], c, tig + 4);
            unsigned bl0 = ldb(Bsl[buf], c, tig);
            unsigned bl1 = ldb(Bsl[buf], c, tig + 4);
            unsigned rh0 = ldb(Bsh[buf][1], c, tig);
            unsigned rh1 = ldb(Bsh[buf][1], c, tig + 4);
#pragma unroll
            for (int i = 0; i < 2; i++) {
                mma16(acc[0][i][j], ah[i], bh0, bh1);   // L: x3
                mma16(acc[0][i][j], ah[i], bl0, bl1);
                mma16(acc[0][i][j], al[i], bh0, bh1);
                mma16(acc[1][i][j], ah[i], rh0, rh1);   // R: x1
            }
        }

        if (it + 2 < 8) {
            load_stage((it + 2) % 3, (it + 2) * BK);
            asm volatile("cp.async.commit_group;");
        }
    }

#pragma unroll
    for (int i = 0; i < 2; i++) {
        int rbase = row0 + wm * 32 + i * 16 + gid;
#pragma unroll
        for (int j = 0; j < 4; j++) {
            int c = col0 + wn * 32 + j * 8 + 2 * tig;
            if (rbase < n) {
                *reinterpret_cast<__half2*>(Cl + (size_t)rbase * oc + c) =
                    __floats2half2_rn(acc[0][i][j][0], acc[0][i][j][1]);
                *reinterpret_cast<float2*>(Cr + (size_t)rbase * oc + c) =
                    make_float2(acc[1][i][j][0], acc[1][i][j][1]);
            }
            if (rbase + 8 < n) {
                *reinterpret_cast<__half2*>(Cl + (size_t)(rbase + 8) * oc + c) =
                    __floats2half2_rn(acc[0][i][j][2], acc[0][i][j][3]);
                *reinterpret_cast<float2*>(Cr + (size_t)(rbase + 8) * oc + c) =
                    make_float2(acc[1][i][j][2], acc[1][i][j][3]);
            }
        }
    }
}

// standalone GEMM (layers 1, 2)
__global__ __launch_bounds__(256, 2) void gemm_dual_k(
    const float* __restrict__ A,
    const __half* __restrict__ Blh, const __half* __restrict__ Bll,
    const __half* __restrict__ Brh,
    __half* __restrict__ Cl, float* __restrict__ Cr, int n, int oc)
{
    gemm_tile_body(A, Blh, Bll, Brh, Cl, Cr, n, oc,
                   blockIdx.x * BM, blockIdx.y * BN);
}

// fused: layer-0 GEMM tiles interleaved with edge-index conversion + counting.
// Blocks bx%5==0 (bx<FUSEB) are GEMM tiles; all others convert 256 edges each.
__global__ __launch_bounds__(256, 2) void gemm0_conv_k(
    const float* __restrict__ A,
    const __half* __restrict__ Blh, const __half* __restrict__ Bll,
    const __half* __restrict__ Brh,
    __half* __restrict__ Cl, float* __restrict__ Cr,
    const void* __restrict__ ei)
{
    const int bx = blockIdx.x;
    const bool isGemm = (bx < FUSEB) && (bx % 5 == 0);
    if (!isGemm) {
        int c = (bx < FUSEB) ? bx - (bx + 4) / 5 : bx - GTILES;
        int i = c * 256 + threadIdx.x;
        if (i < ET) {
            int s, d;
            if (i < NE) {
                if (g_is64) {
                    s = (int)((const long long*)ei)[i];
                    d = (int)((const long long*)ei)[NE + i];
                } else {
                    s = ((const int*)ei)[i];
                    d = ((const int*)ei)[NE + i];
                }
            } else {
                s = d = i - NE;                       // appended self loops
            }
            s = min(max(s, 0), NN - 1);
            d = min(max(d, 0), NN - 1);
            g_src[i] = s;
            g_dst[i] = d;
            atomicAdd(&g_deg[d], 1);
        }
        return;
    }
    const int t = bx / 5;
    gemm_tile_body(A, Blh, Bll, Brh, Cl, Cr, NN, 128,
                   (t % 782) * BM, (t / 782) * BN);
}

// ---------------- fused edge kernel (R10 form: single bank, batch-4) ------
template <int H, int CH>
__global__ __launch_bounds__(256) void gat_edge(
    const __half* __restrict__ hl, const float* __restrict__ hr,
    const float* __restrict__ att, const float* __restrict__ bias,
    float* __restrict__ out)
{
    constexpr int V = CH / 32;
    const int w = (blockIdx.x * blockDim.x + threadIdx.x) >> 5;
    const int lane = threadIdx.x & 31;
    if (w >= NN) return;

    float attv[V], hrv[V], acc[V];
#pragma unroll
    for (int v = 0; v < V; v++) attv[v] = att[lane * V + v];

    if (V == 4) {
        float4 t = __ldg(reinterpret_cast<const float4*>(hr) + w * 32 + lane);
        hrv[0] = t.x; hrv[1] = t.y; hrv[2] = t.z; hrv[3] = t.w;
    } else {
        float2 t = __ldg(reinterpret_cast<const float2*>(hr) + w * 32 + lane);
        hrv[0] = t.x; hrv[1] = t.y;
    }
#pragma unroll
    for (int v = 0; v < V; v++) acc[v] = 0.f;

    auto gather = [&](int s, float* hv) {
        if (V == 4) {
            uint2 t = __ldg(reinterpret_cast<const uint2*>(hl) + s * 32 + lane);
            float2 f01 = __half22float2(*reinterpret_cast<__half2*>(&t.x));
            float2 f23 = __half22float2(*reinterpret_cast<__half2*>(&t.y));
            hv[0] = f01.x; hv[1] = f01.y; hv[2] = f23.x; hv[3] = f23.y;
        } else {
            unsigned t = __ldg(reinterpret_cast<const unsigned*>(hl) + s * 32 + lane);
            float2 f = __half22float2(*reinterpret_cast<__half2*>(&t));
            hv[0] = f.x; hv[1] = f.y;
        }
    };

    auto score = [&](const float* hv) {
        float p = 0.f;
#pragma unroll
        for (int v = 0; v < V; v++) {
            float t = hv[v] + hrv[v];
            t = (t > 0.f) ? t : 0.2f * t;          // LeakyReLU(0.2)
            p = fmaf(t, attv[v], p);
        }
#pragma unroll
        for (int off = (32 / H) >> 1; off > 0; off >>= 1)
            p += __shfl_xor_sync(0xffffffffu, p, off);
        return p;
    };

    float p_self;
    {
        float hs[V];
        gather(w, hs);
        p_self = score(hs);
    }

    float lsum = 0.f;
    const int e0 = g_rowptr[w], e1 = g_rowptr[w + 1];

    auto update = [&](const float* hv) {
        float p = score(hv);
        float ww = __expf(p - p_self);
        lsum += ww;
#pragma unroll
        for (int v = 0; v < V; v++) acc[v] = fmaf(ww, hv[v], acc[v]);
    };

    int e = e0;
    for (; e + 4 <= e1; e += 4) {
        int s0 = __ldg(&g_esrc[e]);
        int s1 = __ldg(&g_esrc[e + 1]);
        int s2 = __ldg(&g_esrc[e + 2]);
        int s3 = __ldg(&g_esrc[e + 3]);
        float hv0[V], hv1[V], hv2[V], hv3[V];
        gather(s0, hv0); gather(s1, hv1); gather(s2, hv2); gather(s3, hv3);
        update(hv0); update(hv1); update(hv2); update(hv3);
    }
    for (; e < e1; e++) {
        float hv[V];
        gather(__ldg(&g_esrc[e]), hv);
        update(hv);
    }

    float inv = 1.f / (lsum + 1e-16f);
    if (V == 4) {
        float4 o;
        o.x = fmaxf(fmaf(acc[0], inv, bias[lane * 4 + 0]), 0.f);
        o.y = fmaxf(fmaf(acc[1], inv, bias[lane * 4 + 1]), 0.f);
        o.z = fmaxf(fmaf(acc[2], inv, bias[lane * 4 + 2]), 0.f);
        o.w = fmaxf(fmaf(acc[3], inv, bias[lane * 4 + 3]), 0.f);
        reinterpret_cast<float4*>(out)[w * 32 + lane] = o;
    } else {
        float2 o;
        o.x = fmaxf(fmaf(acc[0], inv, bias[lane * 2 + 0]), 0.f);
        o.y = fmaxf(fmaf(acc[1], inv, bias[lane * 2 + 1]), 0.f);
        reinterpret_cast<float2*>(out)[w * 32 + lane] = o;
    }
}

// ---------------- launch ----------------
extern "C" void kernel_launch(void* const* d_in, const int* in_sizes, int n_in,
                              void* d_out, int out_size)
{
    const float* x   = (const float*)d_in[0];
    const void*  ei  = d_in[1];
    const float *W0l = (const float*)d_in[2],  *W0r = (const float*)d_in[3];
    const float *a0  = (const float*)d_in[4],  *b0  = (const float*)d_in[5];
    const float *W1l = (const float*)d_in[6],  *W1r = (const float*)d_in[7];
    const float *a1  = (const float*)d_in[8],  *b1  = (const float*)d_in[9];
    const float *W2l = (const float*)d_in[10], *W2r = (const float*)d_in[11];
    const float *a2  = (const float*)d_in[12], *b2  = (const float*)d_in[13];
    float* out = (float*)d_out;

    void *p_hlh, *p_hr, *p_h, *p_wth, *p_wtl;
    cudaGetSymbolAddress(&p_hlh, g_hlh);
    cudaGetSymbolAddress(&p_hr, g_hr);
    cudaGetSymbolAddress(&p_h, g_h);
    cudaGetSymbolAddress(&p_wth, g_wth);
    cudaGetSymbolAddress(&p_wtl, g_wtl);
    __half* hl  = (__half*)p_hlh;
    float*  hr  = (float*)p_hr;
    float*  h   = (float*)p_h;
    __half* wth = (__half*)p_wth;
    __half* wtl = (__half*)p_wtl;

    const int eb = CONVB;
    const dim3 gg((NN + BM - 1) / BM, 2);
    const dim3 gg2((NN + BM - 1) / BM, 1);
    const int egrid = (NN * 32 + 255) / 256;
    const int fgrid = FUSEB + (CONVB - (FUSEB - GTILES));  // GTILES*5 + rest

    zero_detect_k<<<(NN + 1023) / 1024, 1024>>>((const int*)ei,
        W0l, W0r, W1l, W1r, W2l, W2r);                               // 1
    gemm0_conv_k<<<GTILES + CONVB, 256>>>(x, wth, wtl, wth + 16384,
                                          hl, hr, ei);               // 2
    scan1_k<<<NB, 1024>>>();                                         // 3
    scan3_k<<<(NN + 255) / 256, 256>>>();                            // 4
    scatter_k<<<(ET + 255) / 256, 256>>>();                          // 5
    gat_edge<4, 128><<<egrid, 256>>>(hl, hr, a0, b0, h);             // 6
    gemm_dual_k<<<gg, 256>>>(h, wth + 2 * 16384, wtl + 2 * 16384,
                             wth + 3 * 16384, hl, hr, NN, 128);      // 7
    gat_edge<4, 128><<<egrid, 256>>>(hl, hr, a1, b1, h);             // 8
    gemm_dual_k<<<gg2, 256>>>(h, wth + 4 * 16384, wtl + 4 * 16384,
                              wth + 5 * 16384, hl, hr, NN, 64);      // 9
    gat_edge<1, 64><<<egrid, 256>>>(hl, hr, a2, b2, out);            // 10
}

// round 14
// speedup vs baseline: 1.1242x; 1.0240x over previous
#include <cuda_runtime.h>
#include <cuda_fp16.h>
#include <math.h>

#define NN 100000
#define NE 1600000
#define ET 1700000          // NE + NN self loops
#define NB 98               // ceil(NN/1024)

// GEMM tiling
#define BM 128
#define BN 64
#define BK 16

#define GTILES 1564         // 782 x 2 tiles for the 128-col GEMM
#define CONVB 6641          // ceil(ET/256) convert blocks
#define FUSEB (GTILES * 5)  // gemm blocks sit at bx%5==0, bx<FUSEB

// ---------------- static scratch (no allocations allowed) ----------------
__device__ __align__(256) __half g_hlh[NN * 128];   // hl fp16 (edge gather)
__device__ __align__(256) float  g_hr[NN * 128];
__device__ __align__(256) float  g_h [NN * 128];
__device__ __align__(256) __half g_wth[6 * 16384];  // W^T [oc][128], fp16 hi
__device__ __align__(256) __half g_wtl[6 * 16384];  // W^T lo residual
__device__ int g_deg[NN];
__device__ int g_tmp[NN];
__device__ int g_rowptr[NN + 1];
__device__ int g_fill[NN];
__device__ int g_esrc[ET];
__device__ int g_src[ET];
__device__ int g_dst[ET];
__device__ int g_bsums[128];
__device__ int g_is64;

// ---------------- setup: zero deg, detect dtype (parallel), convert W ----
__global__ void zero_detect_k(const int* __restrict__ ei32,
                              const float* __restrict__ W0l, const float* __restrict__ W0r,
                              const float* __restrict__ W1l, const float* __restrict__ W1r,
                              const float* __restrict__ W2l, const float* __restrict__ W2r) {
    int i = blockIdx.x * blockDim.x + threadIdx.x;
    if (i < NN) g_deg[i] = 0;
    // parallel dtype detect: one warp, 32 loads/lane + OR-reduce
    if (blockIdx.x == 0 && threadIdx.x < 32) {
        int acc = 0;
        for (int j = threadIdx.x; j < 1024; j += 32) acc |= ei32[2 * j + 1];
#pragma unroll
        for (int off = 16; off > 0; off >>= 1)
            acc |= __shfl_xor_sync(0xffffffffu, acc, off);
        if (threadIdx.x == 0) g_is64 = (acc == 0) ? 1 : 0;
    }
    // W transpose + fp16 hi/lo split: Wt[oc][128] so k runs contiguous
    if (i < 4 * 16384) {
        int mat = i >> 14, idx = i & 16383;
        const float* Ws[4] = {W0l, W0r, W1l, W1r};
        float w = Ws[mat][idx];
        int k = idx >> 7, o = idx & 127;        // src W[k][128]
        __half hi = __float2half_rn(w);
        __half lo = __float2half_rn(w - __half2float(hi));
        g_wth[mat * 16384 + o * 128 + k] = hi;
        g_wtl[mat * 16384 + o * 128 + k] = lo;
    } else if (i < 4 * 16384 + 2 * 8192) {
        int j = i - 65536;
        int mat = 4 + (j >> 13), idx = j & 8191;
        const float* Ws2[2] = {W2l, W2r};
        float w = Ws2[mat - 4][idx];
        int k = idx >> 6, o = idx & 63;         // src W2[k][64]
        __half hi = __float2half_rn(w);
        __half lo = __float2half_rn(w - __half2float(hi));
        g_wth[mat * 16384 + o * 128 + k] = hi;
        g_wtl[mat * 16384 + o * 128 + k] = lo;
    }
}

__global__ void scan1_k() {
    __shared__ int sh[1024];
    int i = blockIdx.x * 1024 + threadIdx.x;
    int v = (i < NN) ? g_deg[i] : 0;
    sh[threadIdx.x] = v;
    __syncthreads();
    for (int off = 1; off < 1024; off <<= 1) {
        int t = (threadIdx.x >= off) ? sh[threadIdx.x - off] : 0;
        __syncthreads();
        sh[threadIdx.x] += t;
        __syncthreads();
    }
    if (i < NN) g_tmp[i] = sh[threadIdx.x];
    if (threadIdx.x == 1023) g_bsums[blockIdx.x] = sh[1023];
}

// fused scan2+scan3
__global__ void scan3_k() {
    __shared__ int pref[NB + 1];
    if (threadIdx.x == 0) {
        int acc = 0;
        for (int b = 0; b < NB; b++) { pref[b] = acc; acc += g_bsums[b]; }
    }
    __syncthreads();
    int i = blockIdx.x * blockDim.x + threadIdx.x;
    if (i < NN) {
        int incl = g_tmp[i] + pref[i >> 10];
        g_rowptr[i + 1] = incl;
        g_fill[i] = incl - g_deg[i];           // exclusive prefix = fill cursor
    }
    if (i == 0) g_rowptr[0] = 0;
}

__global__ void scatter_k() {
    int i = blockIdx.x * blockDim.x + threadIdx.x;
    if (i >= ET) return;
    int pos = atomicAdd(&g_fill[g_dst[i]], 1);
    g_esrc[pos] = g_src[i];
}

// ---------------- asymmetric dual tensor-core GEMM body -------------------
// L side (hl, aggregated): fp16x3. R side (hr, score-only): plain fp16.
__device__ __forceinline__ void mma16(float* c, const unsigned* a,
                                      unsigned b0, unsigned b1) {
    asm volatile(
        "mma.sync.aligned.m16n8k16.row.col.f32.f16.f16.f32 "
        "{%0,%1,%2,%3}, {%4,%5,%6,%7}, {%8,%9}, {%0,%1,%2,%3};"
        : "+f"(c[0]), "+f"(c[1]), "+f"(c[2]), "+f"(c[3])
        : "r"(a[0]), "r"(a[1]), "r"(a[2]), "r"(a[3]), "r"(b0), "r"(b1));
}

__device__ __forceinline__ void cp16(unsigned dst, const void* src, int srcBytes) {
    asm volatile("cp.async.ca.shared.global [%0], [%1], 16, %2;"
                 :: "r"(dst), "l"(src), "r"(srcBytes));
}

__device__ __forceinline__ void split2(float x, float y, unsigned& hi, unsigned& lo) {
    __half2 h = __floats2half2_rn(x, y);
    __half2 l = __floats2half2_rn(x - __low2float(h), y - __high2float(h));
    hi = *reinterpret_cast<unsigned*>(&h);
    lo = *reinterpret_cast<unsigned*>(&l);
}

// B smem rows of 16 halves (2 x 16B chunks), chunk swizzled by row bit2.
__device__ __forceinline__ unsigned ldb(const __half* buf, int row, int u) {
    int idx = row * 8 + (u ^ (((row >> 2) & 1) << 2));
    return reinterpret_cast<const unsigned*>(buf)[idx];
}

// 3-stage cp.async pipeline, ONE __syncthreads per k-iteration.
__device__ __forceinline__ void gemm_tile_body(
    const float* __restrict__ A,
    const __half* __restrict__ Blh, const __half* __restrict__ Bll,
    const __half* __restrict__ Brh,
    __half* __restrict__ Cl, float* __restrict__ Cr,
    int n, int oc, int row0, int col0)
{
    __shared__ float  As[3][BM * 16];                 // fp32 A, XOR-swizzled
    __shared__ __half Bsh[3][2][BN * 16];             // [stage][side] hi
    __shared__ __half Bsl[3][BN * 16];                // [stage] L-side lo

    const int tid = threadIdx.x;
    const int lane = tid & 31, wid = tid >> 5;
    const int wm = wid >> 1, wn = wid & 1;       // 4 x 2 warp grid
    const int gid = lane >> 2, tig = lane & 3;

    float acc[2][2][4][4];                        // [side][i][j][reg]
#pragma unroll
    for (int sd = 0; sd < 2; sd++)
#pragma unroll
        for (int i = 0; i < 2; i++)
#pragma unroll
            for (int j = 0; j < 4; j++)
#pragma unroll
                for (int r = 0; r < 4; r++) acc[sd][i][j][r] = 0.f;

    const int ar = tid >> 1, kof = (tid & 1) * 8;      // A: 2x16B per thread
    const int aswz = 4 * (ar & 3);
    const int aValid = (row0 + ar < n) ? 16 : 0;
    const int bt = tid & 127, bside = tid >> 7;        // B halves
    const int brr = bt >> 1, bcc = bt & 1;
    const int bOff = brr * 32 + 16 * (bcc ^ ((brr >> 2) & 1));  // bytes

    auto load_stage = [&](int st, int kk) {
        const float* srcA = A + (size_t)(row0 + ar) * 128 + kk + kof;
        cp16((unsigned)__cvta_generic_to_shared(&As[st][ar * 16 + (kof ^ aswz)]),
             srcA, aValid);
        cp16((unsigned)__cvta_generic_to_shared(&As[st][ar * 16 + ((kof + 4) ^ aswz)]),
             srcA + 4, aValid);
        if (bside == 0) {
            const __half* sh = Blh + (size_t)(col0 + brr) * 128 + kk + 8 * bcc;
            const __half* sl = Bll + (size_t)(col0 + brr) * 128 + kk + 8 * bcc;
            cp16((unsigned)__cvta_generic_to_shared(
                     reinterpret_cast<char*>(Bsh[st][0]) + bOff), sh, 16);
            cp16((unsigned)__cvta_generic_to_shared(
                     reinterpret_cast<char*>(Bsl[st]) + bOff), sl, 16);
        } else {
            const __half* sh = Brh + (size_t)(col0 + brr) * 128 + kk + 8 * bcc;
            cp16((unsigned)__cvta_generic_to_shared(
                     reinterpret_cast<char*>(Bsh[st][1]) + bOff), sh, 16);
        }
    };

    load_stage(0, 0);
    asm volatile("cp.async.commit_group;");
    load_stage(1, BK);
    asm volatile("cp.async.commit_group;");

    const int kp0 = 2 * tig;            // A k-pair base
#pragma unroll
    for (int it = 0; it < 8; it++) {
        const int buf = it % 3;
        if (it == 7) asm volatile("cp.async.wait_group 0;");
        else         asm volatile("cp.async.wait_group 1;");
        __syncthreads();   // stage `buf` ready; all warps done with stage (it-1)%3

        unsigned ah[2][4], al[2][4];
#pragma unroll
        for (int i = 0; i < 2; i++) {
            const int m0 = wm * 32 + i * 16;
            const int r0 = m0 + gid, r1 = r0 + 8;
            const int s0 = 4 * (r0 & 3), s1 = 4 * (r1 & 3);
            float2 f0 = *reinterpret_cast<const float2*>(&As[buf][r0 * 16 + (kp0 ^ s0)]);
            float2 f1 = *reinterpret_cast<const float2*>(&As[buf][r1 * 16 + (kp0 ^ s1)]);
            float2 f2 = *reinterpret_cast<const float2*>(&As[buf][r0 * 16 + ((kp0 + 8) ^ s0)]);
            float2 f3 = *reinterpret_cast<const float2*>(&As[buf][r1 * 16 + ((kp0 + 8) ^ s1)]);
            split2(f0.x, f0.y, ah[i][0], al[i][0]);
            split2(f1.x, f1.y, ah[i][1], al[i][1]);
            split2(f2.x, f2.y, ah[i][2], al[i][2]);
            split2(f3.x, f3.y, ah[i][3], al[i][3]);
        }

#pragma unroll
        for (int j = 0; j < 4; j++) {
            const int c = wn * 32 + j * 8 + gid;
            unsigned bh0 = ldb(Bsh[buf][0], c, tig);
            unsigned bh1 = ldb(Bsh[buf][0], c, tig + 4);
            unsigned bl0 = ldb(Bsl[buf], c, tig);
            unsigned bl1 = ldb(Bsl[buf], c, tig + 4);
            unsigned rh0 = ldb(Bsh[buf][1], c, tig);
            unsigned rh1 = ldb(Bsh[buf][1], c, tig + 4);
#pragma unroll
            for (int i = 0; i < 2; i++) {
                mma16(acc[0][i][j], ah[i], bh0, bh1);   // L: x3
                mma16(acc[0][i][j], ah[i], bl0, bl1);
                mma16(acc[0][i][j], al[i], bh0, bh1);
                mma16(acc[1][i][j], ah[i], rh0, rh1);   // R: x1
            }
        }

        if (it + 2 < 8) {
            load_stage((it + 2) % 3, (it + 2) * BK);
            asm volatile("cp.async.commit_group;");
        }
    }

#pragma unroll
    for (int i = 0; i < 2; i++) {
        int rbase = row0 + wm * 32 + i * 16 + gid;
#pragma unroll
        for (int j = 0; j < 4; j++) {
            int c = col0 + wn * 32 + j * 8 + 2 * tig;
            if (rbase < n) {
                *reinterpret_cast<__half2*>(Cl + (size_t)rbase * oc + c) =
                    __floats2half2_rn(acc[0][i][j][0], acc[0][i][j][1]);
                *reinterpret_cast<float2*>(Cr + (size_t)rbase * oc + c) =
                    make_float2(acc[1][i][j][0], acc[1][i][j][1]);
            }
            if (rbase + 8 < n) {
                *reinterpret_cast<__half2*>(Cl + (size_t)(rbase + 8) * oc + c) =
                    __floats2half2_rn(acc[0][i][j][2], acc[0][i][j][3]);
                *reinterpret_cast<float2*>(Cr + (size_t)(rbase + 8) * oc + c) =
                    make_float2(acc[1][i][j][2], acc[1][i][j][3]);
            }
        }
    }
}

// standalone GEMM (layers 1, 2)
__global__ __launch_bounds__(256, 2) void gemm_dual_k(
    const float* __restrict__ A,
    const __half* __restrict__ Blh, const __half* __restrict__ Bll,
    const __half* __restrict__ Brh,
    __half* __restrict__ Cl, float* __restrict__ Cr, int n, int oc)
{
    gemm_tile_body(A, Blh, Bll, Brh, Cl, Cr, n, oc,
                   blockIdx.x * BM, blockIdx.y * BN);
}

// fused: layer-0 GEMM tiles interleaved with edge-index conversion + counting.
__global__ __launch_bounds__(256, 2) void gemm0_conv_k(
    const float* __restrict__ A,
    const __half* __restrict__ Blh, const __half* __restrict__ Bll,
    const __half* __restrict__ Brh,
    __half* __restrict__ Cl, float* __restrict__ Cr,
    const void* __restrict__ ei)
{
    const int bx = blockIdx.x;
    const bool isGemm = (bx < FUSEB) && (bx % 5 == 0);
    if (!isGemm) {
        int c = (bx < FUSEB) ? bx - (bx + 4) / 5 : bx - GTILES;
        int i = c * 256 + threadIdx.x;
        if (i < ET) {
            int s, d;
            if (i < NE) {
                if (g_is64) {
                    s = (int)((const long long*)ei)[i];
                    d = (int)((const long long*)ei)[NE + i];
                } else {
                    s = ((const int*)ei)[i];
                    d = ((const int*)ei)[NE + i];
                }
            } else {
                s = d = i - NE;                       // appended self loops
            }
            s = min(max(s, 0), NN - 1);
            d = min(max(d, 0), NN - 1);
            g_src[i] = s;
            g_dst[i] = d;
            atomicAdd(&g_deg[d], 1);
        }
        return;
    }
    const int t = bx / 5;
    gemm_tile_body(A, Blh, Bll, Brh, Cl, Cr, NN, 128,
                   (t % 782) * BM, (t / 782) * BN);
}

// ---------------- fused edge kernel: batch-of-8 gathers (8-deep MLP) ------
template <int H, int CH>
__global__ __launch_bounds__(256) void gat_edge(
    const __half* __restrict__ hl, const float* __restrict__ hr,
    const float* __restrict__ att, const float* __restrict__ bias,
    float* __restrict__ out)
{
    constexpr int V = CH / 32;
    const int w = (blockIdx.x * blockDim.x + threadIdx.x) >> 5;
    const int lane = threadIdx.x & 31;
    if (w >= NN) return;

    float attv[V], hrv[V], acc[V];
#pragma unroll
    for (int v = 0; v < V; v++) attv[v] = att[lane * V + v];

    if (V == 4) {
        float4 t = __ldg(reinterpret_cast<const float4*>(hr) + w * 32 + lane);
        hrv[0] = t.x; hrv[1] = t.y; hrv[2] = t.z; hrv[3] = t.w;
    } else {
        float2 t = __ldg(reinterpret_cast<const float2*>(hr) + w * 32 + lane);
        hrv[0] = t.x; hrv[1] = t.y;
    }
#pragma unroll
    for (int v = 0; v < V; v++) acc[v] = 0.f;

    const uint2* hl2 = reinterpret_cast<const uint2*>(hl);
    const unsigned* hl1 = reinterpret_cast<const unsigned*>(hl);

    auto graw = [&](int s) -> uint2 {
        if (V == 4) return __ldg(hl2 + s * 32 + lane);
        uint2 r; r.x = __ldg(hl1 + s * 32 + lane); r.y = 0; return r;
    };
    auto score = [&](const float* hv) {
        float p = 0.f;
#pragma unroll
        for (int v = 0; v < V; v++) {
            float t = hv[v] + hrv[v];
            t = (t > 0.f) ? t : 0.2f * t;          // LeakyReLU(0.2)
            p = fmaf(t, attv[v], p);
        }
#pragma unroll
        for (int off = (32 / H) >> 1; off > 0; off >>= 1)
            p += __shfl_xor_sync(0xffffffffu, p, off);
        return p;
    };

    float p_self;
    {
        uint2 raw = graw(w);
        float hs[V];
        float2 f01 = __half22float2(*reinterpret_cast<__half2*>(&raw.x));
        hs[0] = f01.x; hs[1] = f01.y;
        if (V == 4) {
            float2 f23 = __half22float2(*reinterpret_cast<__half2*>(&raw.y));
            hs[2] = f23.x; hs[3] = f23.y;
        }
        p_self = score(hs);
    }

    float lsum = 0.f;
    auto update = [&](uint2 raw) {
        float hv[V];
        float2 f01 = __half22float2(*reinterpret_cast<__half2*>(&raw.x));
        hv[0] = f01.x; hv[1] = f01.y;
        if (V == 4) {
            float2 f23 = __half22float2(*reinterpret_cast<__half2*>(&raw.y));
            hv[2] = f23.x; hv[3] = f23.y;
        }
        float p = score(hv);
        float ww = __expf(p - p_self);
        lsum += ww;
#pragma unroll
        for (int v = 0; v < V; v++) acc[v] = fmaf(ww, hv[v], acc[v]);
    };

    const int e0 = g_rowptr[w], e1 = g_rowptr[w + 1];
    int e = e0;
    // batch of 8: all index loads, then all gathers, then all updates
    for (; e + 8 <= e1; e += 8) {
        int s0 = __ldg(&g_esrc[e]);
        int s1 = __ldg(&g_esrc[e + 1]);
        int s2 = __ldg(&g_esrc[e + 2]);
        int s3 = __ldg(&g_esrc[e + 3]);
        int s4 = __ldg(&g_esrc[e + 4]);
        int s5 = __ldg(&g_esrc[e + 5]);
        int s6 = __ldg(&g_esrc[e + 6]);
        int s7 = __ldg(&g_esrc[e + 7]);
        uint2 r0 = graw(s0), r1 = graw(s1), r2 = graw(s2), r3 = graw(s3);
        uint2 r4 = graw(s4), r5 = graw(s5), r6 = graw(s6), r7 = graw(s7);
        update(r0); update(r1); update(r2); update(r3);
        update(r4); update(r5); update(r6); update(r7);
    }
    for (; e + 4 <= e1; e += 4) {
        int s0 = __ldg(&g_esrc[e]);
        int s1 = __ldg(&g_esrc[e + 1]);
        int s2 = __ldg(&g_esrc[e + 2]);
        int s3 = __ldg(&g_esrc[e + 3]);
        uint2 r0 = graw(s0), r1 = graw(s1), r2 = graw(s2), r3 = graw(s3);
        update(r0); update(r1); update(r2); update(r3);
    }
    for (; e < e1; e++) {
        update(graw(__ldg(&g_esrc[e])));
    }

    float inv = 1.f / (lsum + 1e-16f);
    if (V == 4) {
        float4 o;
        o.x = fmaxf(fmaf(acc[0], inv, bias[lane * 4 + 0]), 0.f);
        o.y = fmaxf(fmaf(acc[1], inv, bias[lane * 4 + 1]), 0.f);
        o.z = fmaxf(fmaf(acc[2], inv, bias[lane * 4 + 2]), 0.f);
        o.w = fmaxf(fmaf(acc[3], inv, bias[lane * 4 + 3]), 0.f);
        reinterpret_cast<float4*>(out)[w * 32 + lane] = o;
    } else {
        float2 o;
        o.x = fmaxf(fmaf(acc[0], inv, bias[lane * 2 + 0]), 0.f);
        o.y = fmaxf(fmaf(acc[1], inv, bias[lane * 2 + 1]), 0.f);
        reinterpret_cast<float2*>(out)[w * 32 + lane] = o;
    }
}

// ---------------- launch ----------------
extern "C" void kernel_launch(void* const* d_in, const int* in_sizes, int n_in,
                              void* d_out, int out_size)
{
    const float* x   = (const float*)d_in[0];
    const void*  ei  = d_in[1];
    const float *W0l = (const float*)d_in[2],  *W0r = (const float*)d_in[3];
    const float *a0  = (const float*)d_in[4],  *b0  = (const float*)d_in[5];
    const float *W1l = (const float*)d_in[6],  *W1r = (const float*)d_in[7];
    const float *a1  = (const float*)d_in[8],  *b1  = (const float*)d_in[9];
    const float *W2l = (const float*)d_in[10], *W2r = (const float*)d_in[11];
    const float *a2  = (const float*)d_in[12], *b2  = (const float*)d_in[13];
    float* out = (float*)d_out;

    void *p_hlh, *p_hr, *p_h, *p_wth, *p_wtl;
    cudaGetSymbolAddress(&p_hlh, g_hlh);
    cudaGetSymbolAddress(&p_hr, g_hr);
    cudaGetSymbolAddress(&p_h, g_h);
    cudaGetSymbolAddress(&p_wth, g_wth);
    cudaGetSymbolAddress(&p_wtl, g_wtl);
    __half* hl  = (__half*)p_hlh;
    float*  hr  = (float*)p_hr;
    float*  h   = (float*)p_h;
    __half* wth = (__half*)p_wth;
    __half* wtl = (__half*)p_wtl;

    const dim3 gg((NN + BM - 1) / BM, 2);
    const dim3 gg2((NN + BM - 1) / BM, 1);
    const int egrid = (NN * 32 + 255) / 256;

    zero_detect_k<<<(NN + 1023) / 1024, 1024>>>((const int*)ei,
        W0l, W0r, W1l, W1r, W2l, W2r);                               // 1
    gemm0_conv_k<<<GTILES + CONVB, 256>>>(x, wth, wtl, wth + 16384,
                                          hl, hr, ei);               // 2
    scan1_k<<<NB, 1024>>>();                                         // 3
    scan3_k<<<(NN + 255) / 256, 256>>>();                            // 4
    scatter_k<<<(ET + 255) / 256, 256>>>();                          // 5
    gat_edge<4, 128><<<egrid, 256>>>(hl, hr, a0, b0, h);             // 6
    gemm_dual_k<<<gg, 256>>>(h, wth + 2 * 16384, wtl + 2 * 16384,
                             wth + 3 * 16384, hl, hr, NN, 128);      // 7
    gat_edge<4, 128><<<egrid, 256>>>(hl, hr, a1, b1, h);             // 8
    gemm_dual_k<<<gg2, 256>>>(h, wth + 4 * 16384, wtl + 4 * 16384,
                              wth + 5 * 16384, hl, hr, NN, 64);      // 9
    gat_edge<1, 64><<<egrid, 256>>>(hl, hr, a2, b2, out);            // 10
}

// round 15
// speedup vs baseline: 1.1950x; 1.0630x over previous
#include <cuda_runtime.h>
#include <cuda_fp16.h>
#include <math.h>

#define NN 100000
#define NE 1600000
#define ET 1700000          // NE + NN self loops
#define NB 98               // ceil(NN/1024)

// GEMM tiling
#define BM 128
#define BN 64
#define BK 16

#define GTILES 1564         // 782 x 2 tiles for the 128-col GEMM
#define CONVB 6641          // ceil(ET/256) convert blocks
#define FUSEB (GTILES * 5)  // gemm blocks sit at bx%5==0, bx<FUSEB

// ---------------- static scratch (no allocations allowed) ----------------
__device__ __align__(256) __half g_hlh[NN * 128];   // hl fp16 (edge gather)
__device__ __align__(256) float  g_hr[NN * 128];
__device__ __align__(256) float  g_h [NN * 128];
__device__ __align__(256) __half g_wth[6 * 16384];  // W^T [oc][128], fp16
__device__ int g_deg[NN];
__device__ int g_tmp[NN];
__device__ int g_rowptr[NN + 1];
__device__ int g_fill[NN];
__device__ int g_esrc[ET];
__device__ int g_src[ET];
__device__ int g_dst[ET];
__device__ int g_bsums[128];
__device__ int g_is64;

// ---------------- setup: zero deg, detect dtype (parallel), convert W ----
__global__ void zero_detect_k(const int* __restrict__ ei32,
                              const float* __restrict__ W0l, const float* __restrict__ W0r,
                              const float* __restrict__ W1l, const float* __restrict__ W1r,
                              const float* __restrict__ W2l, const float* __restrict__ W2r) {
    int i = blockIdx.x * blockDim.x + threadIdx.x;
    if (i < NN) g_deg[i] = 0;
    // parallel dtype detect: one warp, 32 loads/lane + OR-reduce
    if (blockIdx.x == 0 && threadIdx.x < 32) {
        int acc = 0;
        for (int j = threadIdx.x; j < 1024; j += 32) acc |= ei32[2 * j + 1];
#pragma unroll
        for (int off = 16; off > 0; off >>= 1)
            acc |= __shfl_xor_sync(0xffffffffu, acc, off);
        if (threadIdx.x == 0) g_is64 = (acc == 0) ? 1 : 0;
    }
    // W transpose + fp16 convert: Wt[oc][128] so k runs contiguous
    if (i < 4 * 16384) {
        int mat = i >> 14, idx = i & 16383;
        const float* Ws[4] = {W0l, W0r, W1l, W1r};
        float w = Ws[mat][idx];
        int k = idx >> 7, o = idx & 127;        // src W[k][128]
        g_wth[mat * 16384 + o * 128 + k] = __float2half_rn(w);
    } else if (i < 4 * 16384 + 2 * 8192) {
        int j = i - 65536;
        int mat = 4 + (j >> 13), idx = j & 8191;
        const float* Ws2[2] = {W2l, W2r};
        float w = Ws2[mat - 4][idx];
        int k = idx >> 6, o = idx & 63;         // src W2[k][64]
        g_wth[mat * 16384 + o * 128 + k] = __float2half_rn(w);
    }
}

__global__ void scan1_k() {
    __shared__ int sh[1024];
    int i = blockIdx.x * 1024 + threadIdx.x;
    int v = (i < NN) ? g_deg[i] : 0;
    sh[threadIdx.x] = v;
    __syncthreads();
    for (int off = 1; off < 1024; off <<= 1) {
        int t = (threadIdx.x >= off) ? sh[threadIdx.x - off] : 0;
        __syncthreads();
        sh[threadIdx.x] += t;
        __syncthreads();
    }
    if (i < NN) g_tmp[i] = sh[threadIdx.x];
    if (threadIdx.x == 1023) g_bsums[blockIdx.x] = sh[1023];
}

// fused scan2+scan3
__global__ void scan3_k() {
    __shared__ int pref[NB + 1];
    if (threadIdx.x == 0) {
        int acc = 0;
        for (int b = 0; b < NB; b++) { pref[b] = acc; acc += g_bsums[b]; }
    }
    __syncthreads();
    int i = blockIdx.x * blockDim.x + threadIdx.x;
    if (i < NN) {
        int incl = g_tmp[i] + pref[i >> 10];
        g_rowptr[i + 1] = incl;
        g_fill[i] = incl - g_deg[i];           // exclusive prefix = fill cursor
    }
    if (i == 0) g_rowptr[0] = 0;
}

__global__ void scatter_k() {
    int i = blockIdx.x * blockDim.x + threadIdx.x;
    if (i >= ET) return;
    int pos = atomicAdd(&g_fill[g_dst[i]], 1);
    g_esrc[pos] = g_src[i];
}

// ---------------- plain-fp16 dual tensor-core GEMM body -------------------
// Both sides: single fp16 mma, fp32 accumulate. (hl is stored fp16 anyway,
// hr is score-only; dot-product input-rounding ~2e-4 rms is within budget.)
__device__ __forceinline__ void mma16(float* c, const unsigned* a,
                                      unsigned b0, unsigned b1) {
    asm volatile(
        "mma.sync.aligned.m16n8k16.row.col.f32.f16.f16.f32 "
        "{%0,%1,%2,%3}, {%4,%5,%6,%7}, {%8,%9}, {%0,%1,%2,%3};"
        : "+f"(c[0]), "+f"(c[1]), "+f"(c[2]), "+f"(c[3])
        : "r"(a[0]), "r"(a[1]), "r"(a[2]), "r"(a[3]), "r"(b0), "r"(b1));
}

__device__ __forceinline__ void cp16(unsigned dst, const void* src, int srcBytes) {
    asm volatile("cp.async.ca.shared.global [%0], [%1], 16, %2;"
                 :: "r"(dst), "l"(src), "r"(srcBytes));
}

__device__ __forceinline__ unsigned pack2(float x, float y) {
    __half2 h = __floats2half2_rn(x, y);
    return *reinterpret_cast<unsigned*>(&h);
}

// B smem rows of 16 halves (2 x 16B chunks), chunk swizzled by row bit2.
__device__ __forceinline__ unsigned ldb(const __half* buf, int row, int u) {
    int idx = row * 8 + (u ^ (((row >> 2) & 1) << 2));
    return reinterpret_cast<const unsigned*>(buf)[idx];
}

// 3-stage cp.async pipeline, ONE __syncthreads per k-iteration.
__device__ __forceinline__ void gemm_tile_body(
    const float* __restrict__ A,
    const __half* __restrict__ Blh, const __half* __restrict__ Brh,
    __half* __restrict__ Cl, float* __restrict__ Cr,
    int n, int oc, int row0, int col0)
{
    __shared__ float  As[3][BM * 16];                 // fp32 A, XOR-swizzled
    __shared__ __half Bsh[3][2][BN * 16];             // [stage][side]

    const int tid = threadIdx.x;
    const int lane = tid & 31, wid = tid >> 5;
    const int wm = wid >> 1, wn = wid & 1;       // 4 x 2 warp grid
    const int gid = lane >> 2, tig = lane & 3;

    float acc[2][2][4][4];                        // [side][i][j][reg]
#pragma unroll
    for (int sd = 0; sd < 2; sd++)
#pragma unroll
        for (int i = 0; i < 2; i++)
#pragma unroll
            for (int j = 0; j < 4; j++)
#pragma unroll
                for (int r = 0; r < 4; r++) acc[sd][i][j][r] = 0.f;

    const int ar = tid >> 1, kof = (tid & 1) * 8;      // A: 2x16B per thread
    const int aswz = 4 * (ar & 3);
    const int aValid = (row0 + ar < n) ? 16 : 0;
    const int bt = tid & 127, bside = tid >> 7;        // B halves
    const int brr = bt >> 1, bcc = bt & 1;
    const int bOff = brr * 32 + 16 * (bcc ^ ((brr >> 2) & 1));  // bytes

    auto load_stage = [&](int st, int kk) {
        const float* srcA = A + (size_t)(row0 + ar) * 128 + kk + kof;
        cp16((unsigned)__cvta_generic_to_shared(&As[st][ar * 16 + (kof ^ aswz)]),
             srcA, aValid);
        cp16((unsigned)__cvta_generic_to_shared(&As[st][ar * 16 + ((kof + 4) ^ aswz)]),
             srcA + 4, aValid);
        const __half* Bsrc = (bside == 0) ? Blh : Brh;
        const __half* sh = Bsrc + (size_t)(col0 + brr) * 128 + kk + 8 * bcc;
        cp16((unsigned)__cvta_generic_to_shared(
                 reinterpret_cast<char*>(Bsh[st][bside]) + bOff), sh, 16);
    };

    load_stage(0, 0);
    asm volatile("cp.async.commit_group;");
    load_stage(1, BK);
    asm volatile("cp.async.commit_group;");

    const int kp0 = 2 * tig;            // A k-pair base
#pragma unroll
    for (int it = 0; it < 8; it++) {
        const int buf = it % 3;
        if (it == 7) asm volatile("cp.async.wait_group 0;");
        else         asm volatile("cp.async.wait_group 1;");
        __syncthreads();   // stage `buf` ready; all warps done with stage (it-1)%3

        unsigned ah[2][4];
#pragma unroll
        for (int i = 0; i < 2; i++) {
            const int m0 = wm * 32 + i * 16;
            const int r0 = m0 + gid, r1 = r0 + 8;
            const int s0 = 4 * (r0 & 3), s1 = 4 * (r1 & 3);
            float2 f0 = *reinterpret_cast<const float2*>(&As[buf][r0 * 16 + (kp0 ^ s0)]);
            float2 f1 = *reinterpret_cast<const float2*>(&As[buf][r1 * 16 + (kp0 ^ s1)]);
            float2 f2 = *reinterpret_cast<const float2*>(&As[buf][r0 * 16 + ((kp0 + 8) ^ s0)]);
            float2 f3 = *reinterpret_cast<const float2*>(&As[buf][r1 * 16 + ((kp0 + 8) ^ s1)]);
            ah[i][0] = pack2(f0.x, f0.y);
            ah[i][1] = pack2(f1.x, f1.y);
            ah[i][2] = pack2(f2.x, f2.y);
            ah[i][3] = pack2(f3.x, f3.y);
        }

#pragma unroll
        for (int j = 0; j < 4; j++) {
            const int c = wn * 32 + j * 8 + gid;
            unsigned bh0 = ldb(Bsh[buf][0], c, tig);
            unsigned bh1 = ldb(Bsh[buf][0], c, tig + 4);
            unsigned rh0 = ldb(Bsh[buf][1], c, tig);
            unsigned rh1 = ldb(Bsh[buf][1], c, tig + 4);
#pragma unroll
            for (int i = 0; i < 2; i++) {
                mma16(acc[0][i][j], ah[i], bh0, bh1);   // L
                mma16(acc[1][i][j], ah[i], rh0, rh1);   // R
            }
        }

        if (it + 2 < 8) {
            load_stage((it + 2) % 3, (it + 2) * BK);
            asm volatile("cp.async.commit_group;");
        }
    }

#pragma unroll
    for (int i = 0; i < 2; i++) {
        int rbase = row0 + wm * 32 + i * 16 + gid;
#pragma unroll
        for (int j = 0; j < 4; j++) {
            int c = col0 + wn * 32 + j * 8 + 2 * tig;
            if (rbase < n) {
                *reinterpret_cast<__half2*>(Cl + (size_t)rbase * oc + c) =
                    __floats2half2_rn(acc[0][i][j][0], acc[0][i][j][1]);
                *reinterpret_cast<float2*>(Cr + (size_t)rbase * oc + c) =
                    make_float2(acc[1][i][j][0], acc[1][i][j][1]);
            }
            if (rbase + 8 < n) {
                *reinterpret_cast<__half2*>(Cl + (size_t)(rbase + 8) * oc + c) =
                    __floats2half2_rn(acc[0][i][j][2], acc[0][i][j][3]);
                *reinterpret_cast<float2*>(Cr + (size_t)(rbase + 8) * oc + c) =
                    make_float2(acc[1][i][j][2], acc[1][i][j][3]);
            }
        }
    }
}

// standalone GEMM (layers 1, 2)
__global__ __launch_bounds__(256, 2) void gemm_dual_k(
    const float* __restrict__ A,
    const __half* __restrict__ Blh, const __half* __restrict__ Brh,
    __half* __restrict__ Cl, float* __restrict__ Cr, int n, int oc)
{
    gemm_tile_body(A, Blh, Brh, Cl, Cr, n, oc,
                   blockIdx.x * BM, blockIdx.y * BN);
}

// fused: layer-0 GEMM tiles interleaved with edge-index conversion + counting.
__global__ __launch_bounds__(256, 2) void gemm0_conv_k(
    const float* __restrict__ A,
    const __half* __restrict__ Blh, const __half* __restrict__ Brh,
    __half* __restrict__ Cl, float* __restrict__ Cr,
    const void* __restrict__ ei)
{
    const int bx = blockIdx.x;
    const bool isGemm = (bx < FUSEB) && (bx % 5 == 0);
    if (!isGemm) {
        int c = (bx < FUSEB) ? bx - (bx + 4) / 5 : bx - GTILES;
        int i = c * 256 + threadIdx.x;
        if (i < ET) {
            int s, d;
            if (i < NE) {
                if (g_is64) {
                    s = (int)((const long long*)ei)[i];
                    d = (int)((const long long*)ei)[NE + i];
                } else {
                    s = ((const int*)ei)[i];
                    d = ((const int*)ei)[NE + i];
                }
            } else {
                s = d = i - NE;                       // appended self loops
            }
            s = min(max(s, 0), NN - 1);
            d = min(max(d, 0), NN - 1);
            g_src[i] = s;
            g_dst[i] = d;
            atomicAdd(&g_deg[d], 1);
        }
        return;
    }
    const int t = bx / 5;
    gemm_tile_body(A, Blh, Brh, Cl, Cr, NN, 128,
                   (t % 782) * BM, (t / 782) * BN);
}

// ---------------- fused edge kernel: batch-of-8 gathers, exp2-folded ------
template <int H, int CH>
__global__ __launch_bounds__(256) void gat_edge(
    const __half* __restrict__ hl, const float* __restrict__ hr,
    const float* __restrict__ att, const float* __restrict__ bias,
    float* __restrict__ out)
{
    constexpr int V = CH / 32;
    const int w = (blockIdx.x * blockDim.x + threadIdx.x) >> 5;
    const int lane = threadIdx.x & 31;
    if (w >= NN) return;

    float attv[V], hrv[V], acc[V];
#pragma unroll
    for (int v = 0; v < V; v++)
        attv[v] = att[lane * V + v] * 1.4426950408889634f;   // fold log2(e)

    if (V == 4) {
        float4 t = __ldg(reinterpret_cast<const float4*>(hr) + w * 32 + lane);
        hrv[0] = t.x; hrv[1] = t.y; hrv[2] = t.z; hrv[3] = t.w;
    } else {
        float2 t = __ldg(reinterpret_cast<const float2*>(hr) + w * 32 + lane);
        hrv[0] = t.x; hrv[1] = t.y;
    }
#pragma unroll
    for (int v = 0; v < V; v++) acc[v] = 0.f;

    const uint2* hl2 = reinterpret_cast<const uint2*>(hl);
    const unsigned* hl1 = reinterpret_cast<const unsigned*>(hl);

    auto graw = [&](int s) -> uint2 {
        if (V == 4) return __ldg(hl2 + s * 32 + lane);
        uint2 r; r.x = __ldg(hl1 + s * 32 + lane); r.y = 0; return r;
    };
    auto score = [&](const float* hv) {     // returns log2(e) * raw score
        float p = 0.f;
#pragma unroll
        for (int v = 0; v < V; v++) {
            float t = hv[v] + hrv[v];
            t = fmaxf(t, 0.2f * t);                 // LeakyReLU(0.2)
            p = fmaf(t, attv[v], p);
        }
#pragma unroll
        for (int off = (32 / H) >> 1; off > 0; off >>= 1)
            p += __shfl_xor_sync(0xffffffffu, p, off);
        return p;
    };

    float p_self;
    {
        uint2 raw = graw(w);
        float hs[V];
        float2 f01 = __half22float2(*reinterpret_cast<__half2*>(&raw.x));
        hs[0] = f01.x; hs[1] = f01.y;
        if (V == 4) {
            float2 f23 = __half22float2(*reinterpret_cast<__half2*>(&raw.y));
            hs[2] = f23.x; hs[3] = f23.y;
        }
        p_self = score(hs);
    }

    float lsum = 0.f;
    auto update = [&](uint2 raw) {
        float hv[V];
        float2 f01 = __half22float2(*reinterpret_cast<__half2*>(&raw.x));
        hv[0] = f01.x; hv[1] = f01.y;
        if (V == 4) {
            float2 f23 = __half22float2(*reinterpret_cast<__half2*>(&raw.y));
            hv[2] = f23.x; hv[3] = f23.y;
        }
        float p = score(hv);
        float ww = exp2f(p - p_self);               // == exp(raw - raw_self)
        lsum += ww;
#pragma unroll
        for (int v = 0; v < V; v++) acc[v] = fmaf(ww, hv[v], acc[v]);
    };

    const int e0 = g_rowptr[w], e1 = g_rowptr[w + 1];
    int e = e0;
    for (; e + 8 <= e1; e += 8) {
        int s0 = __ldg(&g_esrc[e]);
        int s1 = __ldg(&g_esrc[e + 1]);
        int s2 = __ldg(&g_esrc[e + 2]);
        int s3 = __ldg(&g_esrc[e + 3]);
        int s4 = __ldg(&g_esrc[e + 4]);
        int s5 = __ldg(&g_esrc[e + 5]);
        int s6 = __ldg(&g_esrc[e + 6]);
        int s7 = __ldg(&g_esrc[e + 7]);
        uint2 r0 = graw(s0), r1 = graw(s1), r2 = graw(s2), r3 = graw(s3);
        uint2 r4 = graw(s4), r5 = graw(s5), r6 = graw(s6), r7 = graw(s7);
        update(r0); update(r1); update(r2); update(r3);
        update(r4); update(r5); update(r6); update(r7);
    }
    for (; e + 4 <= e1; e += 4) {
        int s0 = __ldg(&g_esrc[e]);
        int s1 = __ldg(&g_esrc[e + 1]);
        int s2 = __ldg(&g_esrc[e + 2]);
        int s3 = __ldg(&g_esrc[e + 3]);
        uint2 r0 = graw(s0), r1 = graw(s1), r2 = graw(s2), r3 = graw(s3);
        update(r0); update(r1); update(r2); update(r3);
    }
    for (; e < e1; e++) {
        update(graw(__ldg(&g_esrc[e])));
    }

    float inv = 1.f / (lsum + 1e-16f);
    if (V == 4) {
        float4 o;
        o.x = fmaxf(fmaf(acc[0], inv, bias[lane * 4 + 0]), 0.f);
        o.y = fmaxf(fmaf(acc[1], inv, bias[lane * 4 + 1]), 0.f);
        o.z = fmaxf(fmaf(acc[2], inv, bias[lane * 4 + 2]), 0.f);
        o.w = fmaxf(fmaf(acc[3], inv, bias[lane * 4 + 3]), 0.f);
        reinterpret_cast<float4*>(out)[w * 32 + lane] = o;
    } else {
        float2 o;
        o.x = fmaxf(fmaf(acc[0], inv, bias[lane * 2 + 0]), 0.f);
        o.y = fmaxf(fmaf(acc[1], inv, bias[lane * 2 + 1]), 0.f);
        reinterpret_cast<float2*>(out)[w * 32 + lane] = o;
    }
}

// ---------------- launch ----------------
extern "C" void kernel_launch(void* const* d_in, const int* in_sizes, int n_in,
                              void* d_out, int out_size)
{
    const float* x   = (const float*)d_in[0];
    const void*  ei  = d_in[1];
    const float *W0l = (const float*)d_in[2],  *W0r = (const float*)d_in[3];
    const float *a0  = (const float*)d_in[4],  *b0  = (const float*)d_in[5];
    const float *W1l = (const float*)d_in[6],  *W1r = (const float*)d_in[7];
    const float *a1  = (const float*)d_in[8],  *b1  = (const float*)d_in[9];
    const float *W2l = (const float*)d_in[10], *W2r = (const float*)d_in[11];
    const float *a2  = (const float*)d_in[12], *b2  = (const float*)d_in[13];
    float* out = (float*)d_out;

    void *p_hlh, *p_hr, *p_h, *p_wth;
    cudaGetSymbolAddress(&p_hlh, g_hlh);
    cudaGetSymbolAddress(&p_hr, g_hr);
    cudaGetSymbolAddress(&p_h, g_h);
    cudaGetSymbolAddress(&p_wth, g_wth);
    __half* hl  = (__half*)p_hlh;
    float*  hr  = (float*)p_hr;
    float*  h   = (float*)p_h;
    __half* wth = (__half*)p_wth;

    const dim3 gg((NN + BM - 1) / BM, 2);
    const dim3 gg2((NN + BM - 1) / BM, 1);
    const int egrid = (NN * 32 + 255) / 256;

    zero_detect_k<<<(NN + 1023) / 1024, 1024>>>((const int*)ei,
        W0l, W0r, W1l, W1r, W2l, W2r);                               // 1
    gemm0_conv_k<<<GTILES + CONVB, 256>>>(x, wth, wth + 16384,
                                          hl, hr, ei);               // 2
    scan1_k<<<NB, 1024>>>();                                         // 3
    scan3_k<<<(NN + 255) / 256, 256>>>();                            // 4
    scatter_k<<<(ET + 255) / 256, 256>>>();                          // 5
    gat_edge<4, 128><<<egrid, 256>>>(hl, hr, a0, b0, h);             // 6
    gemm_dual_k<<<gg, 256>>>(h, wth + 2 * 16384,
                             wth + 3 * 16384, hl, hr, NN, 128);      // 7
    gat_edge<4, 128><<<egrid, 256>>>(hl, hr, a1, b1, h);             // 8
    gemm_dual_k<<<gg2, 256>>>(h, wth + 4 * 16384,
                              wth + 5 * 16384, hl, hr, NN, 64);      // 9
    gat_edge<1, 64><<<egrid, 256>>>(hl, hr, a2, b2, out);            // 10
}